// round 1
// baseline (speedup 1.0000x reference)
#include <cuda_runtime.h>
#include <cstdint>

// ---------------------------------------------------------------------------
// PerceiverAttention baseline (fp32 FFMA), sm_103a
//
// Pipeline:
//   1) ln_kernel     : LN(x) and LN(latents) -> g_kvin (concat), g_ln (latents only)
//   2) sgemm         : g_kvin @ Wkv -> g_kv   (33280 x 2048)   [dominant cost]
//   3) sgemm         : g_ln   @ Wq  -> g_q    (512 x 1024)
//   4) attn_kernel   : flash attention over 4160 keys -> g_attn (b,l,heads*dh)
//   5) sgemm         : g_attn @ Wout -> d_out (512 x 1024)
// ---------------------------------------------------------------------------

#define BATCH 8
#define N1 4096
#define N2 64
#define NKEYS 4160          // N1 + N2
#define DIM 1024
#define HEADS 16
#define DH 64
#define MROWS (BATCH * NKEYS)   // 33280

// Scratch (device globals: no allocation allowed in kernel_launch)
__device__ float g_kvin[(size_t)MROWS * DIM];        // LN(x) ++ LN(latents), per batch
__device__ float g_ln  [(size_t)BATCH * N2 * DIM];   // LN(latents), contiguous
__device__ float g_q   [(size_t)BATCH * N2 * DIM];   // q projection
__device__ float g_kv  [(size_t)MROWS * 2 * DIM];    // k (cols 0..1023) | v (cols 1024..2047)
__device__ float g_attn[(size_t)BATCH * N2 * DIM];   // attention output (b, l, heads*dh)

// ---------------------------------------------------------------------------
// LayerNorm: one block per row (1024 elements), 256 threads, float4 loads.
// Rows 0..4095 of each batch come from x (ln1 params), rows 4096..4159 from
// latents (ln2 params, also mirrored into g_ln).
// ---------------------------------------------------------------------------
__global__ __launch_bounds__(256) void ln_kernel(
    const float* __restrict__ x, const float* __restrict__ lat,
    const float* __restrict__ g1, const float* __restrict__ b1,
    const float* __restrict__ g2, const float* __restrict__ b2)
{
    __shared__ float red[16];
    const int r  = blockIdx.x;            // 0..MROWS-1
    const int bb = r / NKEYS;
    const int i  = r - bb * NKEYS;

    const float* src;
    const float* g;
    const float* be;
    float* dst2 = nullptr;
    if (i < N1) {
        src = x + ((size_t)bb * N1 + i) * DIM;
        g = g1; be = b1;
    } else {
        const int j = i - N1;
        src = lat + ((size_t)bb * N2 + j) * DIM;
        g = g2; be = b2;
        dst2 = g_ln + ((size_t)bb * N2 + j) * DIM;
    }
    float* dst = g_kvin + (size_t)r * DIM;

    const int t = threadIdx.x;
    float4 v = reinterpret_cast<const float4*>(src)[t];
    float s  = v.x + v.y + v.z + v.w;
    float sq = v.x * v.x + v.y * v.y + v.z * v.z + v.w * v.w;
    #pragma unroll
    for (int o = 16; o > 0; o >>= 1) {
        s  += __shfl_xor_sync(0xffffffffu, s, o);
        sq += __shfl_xor_sync(0xffffffffu, sq, o);
    }
    if ((t & 31) == 0) { red[t >> 5] = s; red[8 + (t >> 5)] = sq; }
    __syncthreads();
    float S = 0.f, SQ = 0.f;
    #pragma unroll
    for (int k = 0; k < 8; k++) { S += red[k]; SQ += red[8 + k]; }

    const float mu   = S * (1.0f / DIM);
    const float var  = SQ * (1.0f / DIM) - mu * mu;
    const float rstd = rsqrtf(var + 1e-5f);

    float4 gv = reinterpret_cast<const float4*>(g)[t];
    float4 bv = reinterpret_cast<const float4*>(be)[t];
    float4 o;
    o.x = (v.x - mu) * rstd * gv.x + bv.x;
    o.y = (v.y - mu) * rstd * gv.y + bv.y;
    o.z = (v.z - mu) * rstd * gv.z + bv.z;
    o.w = (v.w - mu) * rstd * gv.w + bv.w;
    reinterpret_cast<float4*>(dst)[t] = o;
    if (dst2) reinterpret_cast<float4*>(dst2)[t] = o;
}

// ---------------------------------------------------------------------------
// SGEMM: C[M,N] = A[M,K] @ B[K,N], all row-major. 128x128x16 tile, 256 threads,
// 8x8 microtile. All problem dims are multiples of the tile so no bounds checks.
// ---------------------------------------------------------------------------
__global__ __launch_bounds__(256) void sgemm(
    const float* __restrict__ A, const float* __restrict__ B,
    float* __restrict__ C, int M, int N, int K)
{
    __shared__ float As[16 * 128];   // [k][m] (transposed A tile)
    __shared__ float Bs[16 * 128];   // [k][n]

    const int tid = threadIdx.x;
    const int tx = tid & 15;
    const int ty = tid >> 4;
    const int bx = blockIdx.x;
    const int by = blockIdx.y;

    const int aRow = tid >> 2;            // 0..63 (+64)
    const int aCol = (tid & 3) << 2;      // 0,4,8,12
    const int bRow = tid >> 5;            // 0..7 (+8)
    const int bCol = (tid & 31) << 2;     // 0..124

    const float* Aptr = A + (size_t)by * 128 * K;
    const float* Bptr = B + (size_t)bx * 128;

    float acc[8][8] = {};

    for (int k0 = 0; k0 < K; k0 += 16) {
        #pragma unroll
        for (int p = 0; p < 2; p++) {
            const int r = aRow + p * 64;
            float4 v = *reinterpret_cast<const float4*>(Aptr + (size_t)r * K + k0 + aCol);
            As[(aCol + 0) * 128 + r] = v.x;
            As[(aCol + 1) * 128 + r] = v.y;
            As[(aCol + 2) * 128 + r] = v.z;
            As[(aCol + 3) * 128 + r] = v.w;
        }
        #pragma unroll
        for (int p = 0; p < 2; p++) {
            const int r = bRow + p * 8;
            *reinterpret_cast<float4*>(Bs + r * 128 + bCol) =
                *reinterpret_cast<const float4*>(Bptr + (size_t)(k0 + r) * N + bCol);
        }
        __syncthreads();

        #pragma unroll
        for (int kk = 0; kk < 16; kk++) {
            float a[8], bq[8];
            float4 a0 = *reinterpret_cast<const float4*>(As + kk * 128 + ty * 8);
            float4 a1 = *reinterpret_cast<const float4*>(As + kk * 128 + ty * 8 + 4);
            float4 b0 = *reinterpret_cast<const float4*>(Bs + kk * 128 + tx * 8);
            float4 b1 = *reinterpret_cast<const float4*>(Bs + kk * 128 + tx * 8 + 4);
            a[0]=a0.x; a[1]=a0.y; a[2]=a0.z; a[3]=a0.w;
            a[4]=a1.x; a[5]=a1.y; a[6]=a1.z; a[7]=a1.w;
            bq[0]=b0.x; bq[1]=b0.y; bq[2]=b0.z; bq[3]=b0.w;
            bq[4]=b1.x; bq[5]=b1.y; bq[6]=b1.z; bq[7]=b1.w;
            #pragma unroll
            for (int ii = 0; ii < 8; ii++)
                #pragma unroll
                for (int jj = 0; jj < 8; jj++)
                    acc[ii][jj] += a[ii] * bq[jj];
        }
        __syncthreads();
    }

    float* Cp = C + (size_t)(by * 128 + ty * 8) * N + bx * 128 + tx * 8;
    #pragma unroll
    for (int ii = 0; ii < 8; ii++) {
        float4 o0 = make_float4(acc[ii][0], acc[ii][1], acc[ii][2], acc[ii][3]);
        float4 o1 = make_float4(acc[ii][4], acc[ii][5], acc[ii][6], acc[ii][7]);
        *reinterpret_cast<float4*>(Cp + (size_t)ii * N)     = o0;
        *reinterpret_cast<float4*>(Cp + (size_t)ii * N + 4) = o1;
    }
}

// ---------------------------------------------------------------------------
// Flash attention: one block per (b, h) = 128 blocks, 256 threads.
// Q tile 64x64 (q pre-scaled by 0.125 = dh^-0.5), keys streamed in 64-chunks
// (65 chunks over 4160 keys), online softmax, 4x4 register microtiles.
// smem: 48KB exactly (qs_t[d][q], ks_t[d][k] (reused as P[q][k]), vs[k][d]).
// Mask bias (mask-1)*100 added for the first 4096 keys; 0 for latent keys.
// ---------------------------------------------------------------------------
__global__ __launch_bounds__(256) void attn_kernel(const float* __restrict__ mask)
{
    __shared__ float qs_t[64 * 64];   // [d][q]
    __shared__ float ks_t[64 * 64];   // [d][k]; reused as P[q][k]
    __shared__ float vs  [64 * 64];   // [k][d]

    const int h = blockIdx.x;
    const int b = blockIdx.y;
    const int tid = threadIdx.x;
    const int tq = tid >> 4;   // 0..15 (q-group)
    const int tx = tid & 15;   // 0..15 (k-group / d-group)

    // Load Q (scaled, transposed into [d][q])
    {
        const int qr = tid >> 2;
        const int dg = tid & 3;
        const float4* src = reinterpret_cast<const float4*>(
            g_q + ((size_t)(b * N2 + qr)) * DIM + h * DH + dg * 16);
        #pragma unroll
        for (int ii = 0; ii < 4; ii++) {
            float4 v = src[ii];
            const int d0 = dg * 16 + ii * 4;
            qs_t[(d0 + 0) * 64 + qr] = v.x * 0.125f;
            qs_t[(d0 + 1) * 64 + qr] = v.y * 0.125f;
            qs_t[(d0 + 2) * 64 + qr] = v.z * 0.125f;
            qs_t[(d0 + 3) * 64 + qr] = v.w * 0.125f;
        }
    }

    float O[4][4] = {};
    float m[4], l[4];
    #pragma unroll
    for (int i = 0; i < 4; i++) { m[i] = -1e30f; l[i] = 0.f; }

    const size_t kvbase = (size_t)b * NKEYS * (2 * DIM);

    for (int ch = 0; ch < NKEYS / 64; ch++) {
        const int key0 = ch * 64;
        __syncthreads();   // prior chunk's P/V reads complete; also fences Q load on ch==0

        // Load K chunk (transposed [d][k]) and V chunk ([k][d])
        {
            const int kl = tid >> 2;
            const int dg = tid & 3;
            const float4* ksrc = reinterpret_cast<const float4*>(
                g_kv + kvbase + (size_t)(key0 + kl) * (2 * DIM) + h * DH + dg * 16);
            #pragma unroll
            for (int ii = 0; ii < 4; ii++) {
                float4 v = ksrc[ii];
                const int d0 = dg * 16 + ii * 4;
                ks_t[(d0 + 0) * 64 + kl] = v.x;
                ks_t[(d0 + 1) * 64 + kl] = v.y;
                ks_t[(d0 + 2) * 64 + kl] = v.z;
                ks_t[(d0 + 3) * 64 + kl] = v.w;
            }
            const float4* vsrc = reinterpret_cast<const float4*>(
                g_kv + kvbase + (size_t)(key0 + kl) * (2 * DIM) + DIM + h * DH + dg * 16);
            float4* vdst = reinterpret_cast<float4*>(vs + kl * 64 + dg * 16);
            #pragma unroll
            for (int ii = 0; ii < 4; ii++) vdst[ii] = vsrc[ii];
        }
        __syncthreads();

        // Scores: 4x4 outer product over d
        float acc[4][4] = {};
        #pragma unroll 8
        for (int d = 0; d < 64; d++) {
            float4 av = *reinterpret_cast<const float4*>(qs_t + d * 64 + tq * 4);
            float4 bv = *reinterpret_cast<const float4*>(ks_t + d * 64 + tx * 4);
            float a[4] = {av.x, av.y, av.z, av.w};
            float kb[4] = {bv.x, bv.y, bv.z, bv.w};
            #pragma unroll
            for (int i = 0; i < 4; i++)
                #pragma unroll
                for (int j = 0; j < 4; j++)
                    acc[i][j] += a[i] * kb[j];
        }

        // Additive mask bias per key
        #pragma unroll
        for (int j = 0; j < 4; j++) {
            const int kg = key0 + tx * 4 + j;
            float bias = 0.f;
            if (kg < N1) bias = (mask[(size_t)b * N1 + kg] - 1.0f) * 100.0f;
            #pragma unroll
            for (int i = 0; i < 4; i++) acc[i][j] += bias;
        }

        // Online softmax (row reduction across the 16 tx lanes of this tq group)
        float alpha[4];
        #pragma unroll
        for (int i = 0; i < 4; i++) {
            float cm = fmaxf(fmaxf(acc[i][0], acc[i][1]), fmaxf(acc[i][2], acc[i][3]));
            #pragma unroll
            for (int o = 1; o < 16; o <<= 1)
                cm = fmaxf(cm, __shfl_xor_sync(0xffffffffu, cm, o));
            const float mn = fmaxf(m[i], cm);
            alpha[i] = __expf(m[i] - mn);
            float cl = 0.f;
            #pragma unroll
            for (int j = 0; j < 4; j++) {
                const float p = __expf(acc[i][j] - mn);
                acc[i][j] = p;
                cl += p;
            }
            #pragma unroll
            for (int o = 1; o < 16; o <<= 1)
                cl += __shfl_xor_sync(0xffffffffu, cl, o);
            l[i] = l[i] * alpha[i] + cl;
            m[i] = mn;
            #pragma unroll
            for (int j = 0; j < 4; j++) O[i][j] *= alpha[i];
        }

        __syncthreads();   // all ks_t reads done before P overwrites it
        #pragma unroll
        for (int i = 0; i < 4; i++)
            #pragma unroll
            for (int j = 0; j < 4; j++)
                ks_t[(tq * 4 + i) * 64 + tx * 4 + j] = acc[i][j];
        __syncthreads();

        // PV: O[q][d] += P[q][k] * V[k][d]
        #pragma unroll 8
        for (int k = 0; k < 64; k++) {
            float p0 = ks_t[(tq * 4 + 0) * 64 + k];
            float p1 = ks_t[(tq * 4 + 1) * 64 + k];
            float p2 = ks_t[(tq * 4 + 2) * 64 + k];
            float p3 = ks_t[(tq * 4 + 3) * 64 + k];
            float4 vv = *reinterpret_cast<const float4*>(vs + k * 64 + tx * 4);
            float v4[4] = {vv.x, vv.y, vv.z, vv.w};
            #pragma unroll
            for (int j = 0; j < 4; j++) {
                O[0][j] += p0 * v4[j];
                O[1][j] += p1 * v4[j];
                O[2][j] += p2 * v4[j];
                O[3][j] += p3 * v4[j];
            }
        }
    }

    // Epilogue: O /= l, write to (b, q, h*dh + d)
    #pragma unroll
    for (int i = 0; i < 4; i++) {
        const float inv = 1.0f / l[i];
        float4 o = make_float4(O[i][0] * inv, O[i][1] * inv, O[i][2] * inv, O[i][3] * inv);
        *reinterpret_cast<float4*>(
            g_attn + ((size_t)(b * N2 + tq * 4 + i)) * DIM + h * DH + tx * 4) = o;
    }
}

// ---------------------------------------------------------------------------
// Launch
// ---------------------------------------------------------------------------
extern "C" void kernel_launch(void* const* d_in, const int* in_sizes, int n_in,
                              void* d_out, int out_size)
{
    const float* x       = (const float*)d_in[0];
    const float* latents = (const float*)d_in[1];
    const float* mask    = (const float*)d_in[2];
    const float* ln1g    = (const float*)d_in[3];
    const float* ln1b    = (const float*)d_in[4];
    const float* ln2g    = (const float*)d_in[5];
    const float* ln2b    = (const float*)d_in[6];
    const float* Wq      = (const float*)d_in[7];
    const float* Wkv     = (const float*)d_in[8];
    const float* Wout    = (const float*)d_in[9];
    float* out = (float*)d_out;

    float *p_kvin, *p_ln, *p_q, *p_kv, *p_attn;
    cudaGetSymbolAddress((void**)&p_kvin, g_kvin);
    cudaGetSymbolAddress((void**)&p_ln,   g_ln);
    cudaGetSymbolAddress((void**)&p_q,    g_q);
    cudaGetSymbolAddress((void**)&p_kv,   g_kv);
    cudaGetSymbolAddress((void**)&p_attn, g_attn);

    // 1) LayerNorms -> g_kvin (concat) and g_ln
    ln_kernel<<<MROWS, 256>>>(x, latents, ln1g, ln1b, ln2g, ln2b);

    // 2) KV GEMM: (33280 x 1024) @ (1024 x 2048)
    sgemm<<<dim3(2 * DIM / 128, MROWS / 128), 256>>>(p_kvin, Wkv, p_kv, MROWS, 2 * DIM, DIM);

    // 3) Q GEMM: (512 x 1024) @ (1024 x 1024)
    sgemm<<<dim3(DIM / 128, BATCH * N2 / 128), 256>>>(p_ln, Wq, p_q, BATCH * N2, DIM, DIM);

    // 4) Attention
    attn_kernel<<<dim3(HEADS, BATCH), 256>>>(mask);

    // 5) Output GEMM: (512 x 1024) @ (1024 x 1024) -> d_out
    sgemm<<<dim3(DIM / 128, BATCH * N2 / 128), 256>>>(p_attn, Wout, out, BATCH * N2, DIM, DIM);
}

// round 3
// speedup vs baseline: 2.3048x; 2.3048x over previous
#include <cuda_runtime.h>
#include <cstdint>

// ---------------------------------------------------------------------------
// PerceiverAttention, sm_103 (plain target — no tcgen05; use mma.sync tf32)
//
// Pipeline:
//   0) transpose_kernel : Wkv (1024x2048) -> g_wkvT (2048x1024), tf32-rounded
//   1) ln_kernel        : LN(x), LN(latents) -> g_kvin (tf32-rounded), g_ln
//   2) gemm_tc          : g_kvin @ Wkv -> g_kv (33280 x 2048)  [mma.sync tf32]
//   3) sgemm (fp32)     : g_ln @ Wq -> g_q
//   4) attn_kernel      : flash attention -> g_attn
//   5) sgemm (fp32)     : g_attn @ Wout -> d_out
// ---------------------------------------------------------------------------

#define BATCH 8
#define N1 4096
#define N2 64
#define NKEYS 4160
#define DIM 1024
#define HEADS 16
#define DH 64
#define MROWS (BATCH * NKEYS)   // 33280

__device__ float g_kvin[(size_t)MROWS * DIM];
__device__ float g_ln  [(size_t)BATCH * N2 * DIM];
__device__ float g_q   [(size_t)BATCH * N2 * DIM];
__device__ float g_kv  [(size_t)MROWS * 2 * DIM];
__device__ float g_attn[(size_t)BATCH * N2 * DIM];
__device__ float g_wkvT[(size_t)2 * DIM * DIM];      // Wkv^T (2048 x 1024), tf32-rounded

// ---------------------------------------------------------------------------
// Helpers
// ---------------------------------------------------------------------------
__device__ __forceinline__ uint32_t smem_u32(const void* p) {
    uint32_t a;
    asm("{ .reg .u64 t; cvta.to.shared.u64 t, %1; cvt.u32.u64 %0, t; }" : "=r"(a) : "l"(p));
    return a;
}
__device__ __forceinline__ float f2tf32(float f) {
    uint32_t r;
    asm("cvt.rna.tf32.f32 %0, %1;" : "=r"(r) : "f"(f));
    return __uint_as_float(r);
}
__device__ __forceinline__ void cp_async16(uint32_t dst, const void* src) {
    asm volatile("cp.async.cg.shared.global [%0], [%1], 16;" :: "r"(dst), "l"(src));
}
__device__ __forceinline__ void cp_commit() {
    asm volatile("cp.async.commit_group;" ::: "memory");
}
template <int N>
__device__ __forceinline__ void cp_wait() {
    asm volatile("cp.async.wait_group %0;" :: "n"(N) : "memory");
}
__device__ __forceinline__ void mma_tf32(float* d, const uint32_t* a, const uint32_t* b) {
    asm volatile(
        "mma.sync.aligned.m16n8k8.row.col.f32.tf32.tf32.f32 "
        "{%0,%1,%2,%3}, {%4,%5,%6,%7}, {%8,%9}, {%0,%1,%2,%3};"
        : "+f"(d[0]), "+f"(d[1]), "+f"(d[2]), "+f"(d[3])
        : "r"(a[0]), "r"(a[1]), "r"(a[2]), "r"(a[3]), "r"(b[0]), "r"(b[1]));
}

// ---------------------------------------------------------------------------
// Wkv transpose (tf32-rounded output)
// ---------------------------------------------------------------------------
__global__ __launch_bounds__(256) void transpose_kernel(
    const float* __restrict__ in, float* __restrict__ out)
{
    __shared__ float t[32][33];
    const int bx = blockIdx.x * 32;   // n
    const int by = blockIdx.y * 32;   // k
    const int x = threadIdx.x;
    const int y = threadIdx.y;        // 0..7
    #pragma unroll
    for (int i = 0; i < 32; i += 8)
        t[y + i][x] = f2tf32(in[(size_t)(by + y + i) * (2 * DIM) + bx + x]);
    __syncthreads();
    #pragma unroll
    for (int i = 0; i < 32; i += 8)
        out[(size_t)(bx + y + i) * DIM + by + x] = t[x][y + i];
}

// ---------------------------------------------------------------------------
// LayerNorm: g_kvin gets tf32-rounded values (sole consumer = KV GEMM);
// g_ln keeps full fp32 (feeds Q GEMM).
// ---------------------------------------------------------------------------
__global__ __launch_bounds__(256) void ln_kernel(
    const float* __restrict__ x, const float* __restrict__ lat,
    const float* __restrict__ g1, const float* __restrict__ b1,
    const float* __restrict__ g2, const float* __restrict__ b2)
{
    __shared__ float red[16];
    const int r  = blockIdx.x;
    const int bb = r / NKEYS;
    const int i  = r - bb * NKEYS;

    const float* src;
    const float* g;
    const float* be;
    float* dst2 = nullptr;
    if (i < N1) {
        src = x + ((size_t)bb * N1 + i) * DIM;
        g = g1; be = b1;
    } else {
        const int j = i - N1;
        src = lat + ((size_t)bb * N2 + j) * DIM;
        g = g2; be = b2;
        dst2 = g_ln + ((size_t)bb * N2 + j) * DIM;
    }
    float* dst = g_kvin + (size_t)r * DIM;

    const int t = threadIdx.x;
    float4 v = reinterpret_cast<const float4*>(src)[t];
    float s  = v.x + v.y + v.z + v.w;
    float sq = v.x * v.x + v.y * v.y + v.z * v.z + v.w * v.w;
    #pragma unroll
    for (int o = 16; o > 0; o >>= 1) {
        s  += __shfl_xor_sync(0xffffffffu, s, o);
        sq += __shfl_xor_sync(0xffffffffu, sq, o);
    }
    if ((t & 31) == 0) { red[t >> 5] = s; red[8 + (t >> 5)] = sq; }
    __syncthreads();
    float S = 0.f, SQ = 0.f;
    #pragma unroll
    for (int k = 0; k < 8; k++) { S += red[k]; SQ += red[8 + k]; }

    const float mu   = S * (1.0f / DIM);
    const float var  = SQ * (1.0f / DIM) - mu * mu;
    const float rstd = rsqrtf(var + 1e-5f);

    float4 gv = reinterpret_cast<const float4*>(g)[t];
    float4 bv = reinterpret_cast<const float4*>(be)[t];
    float4 o;
    o.x = (v.x - mu) * rstd * gv.x + bv.x;
    o.y = (v.y - mu) * rstd * gv.y + bv.y;
    o.z = (v.z - mu) * rstd * gv.z + bv.z;
    o.w = (v.w - mu) * rstd * gv.w + bv.w;
    float4 ot;
    ot.x = f2tf32(o.x); ot.y = f2tf32(o.y); ot.z = f2tf32(o.z); ot.w = f2tf32(o.w);
    reinterpret_cast<float4*>(dst)[t] = ot;
    if (dst2) reinterpret_cast<float4*>(dst2)[t] = o;
}

// ---------------------------------------------------------------------------
// tf32 mma.sync GEMM: C[M x N] = A[M x 1024] @ Bt[N x 1024]^T
// CTA tile 128x128, K-chunk 32, cp.async double buffer.
// A and Bt must be pre-rounded to tf32. C row-major, stride ldc.
// ---------------------------------------------------------------------------
#define PADK 36
#define TILE_F (128 * PADK)              // floats per (A or B) stage tile
#define GEMM_SMEM_BYTES (4 * TILE_F * 4) // 2 stages x (A+B) = 73728

__global__ __launch_bounds__(256, 2) void gemm_tc(
    const float* __restrict__ A, const float* __restrict__ Bt,
    float* __restrict__ C, int ldc)
{
    extern __shared__ float sm[];
    // stage s: A at sm + s*2*TILE_F, B at sm + s*2*TILE_F + TILE_F
    const uint32_t sb = smem_u32(sm);

    const int tid  = threadIdx.x;
    const int wid  = tid >> 5;
    const int lane = tid & 31;
    const int wm = wid & 3;          // 0..3 (m)
    const int wn = wid >> 2;         // 0..1 (n)
    const int m0 = blockIdx.y * 128;
    const int n0 = blockIdx.x * 128;

    const float* ga = A  + (size_t)m0 * DIM;
    const float* gb = Bt + (size_t)n0 * DIM;

    // load thread mapping: 1024 16B-chunks per tile, 4 per thread
    const int lr = tid >> 3;         // row base contribution
    const int lc = tid & 7;          // float4 column

    float acc[2][8][4];
    #pragma unroll
    for (int i = 0; i < 2; i++)
        #pragma unroll
        for (int j = 0; j < 8; j++)
            #pragma unroll
            for (int q = 0; q < 4; q++) acc[i][j][q] = 0.f;

    auto load_tile = [&](int chunk, int stage) {
        const uint32_t abase = sb + (uint32_t)stage * 2 * TILE_F * 4;
        const uint32_t bbase = abase + TILE_F * 4;
        const int k0 = chunk * 32;
        #pragma unroll
        for (int i = 0; i < 4; i++) {
            const int r = lr + i * 32;     // 0..127
            cp_async16(abase + (r * PADK + lc * 4) * 4, ga + (size_t)r * DIM + k0 + lc * 4);
        }
        #pragma unroll
        for (int i = 0; i < 4; i++) {
            const int r = lr + i * 32;
            cp_async16(bbase + (r * PADK + lc * 4) * 4, gb + (size_t)r * DIM + k0 + lc * 4);
        }
        cp_commit();
    };

    load_tile(0, 0);

    const int NCHUNK = DIM / 32;   // 32
    for (int c = 0; c < NCHUNK; c++) {
        const int stage = c & 1;
        if (c + 1 < NCHUNK) { load_tile(c + 1, stage ^ 1); cp_wait<1>(); }
        else                { cp_wait<0>(); }
        __syncthreads();

        const uint32_t* As = reinterpret_cast<const uint32_t*>(sm + stage * 2 * TILE_F);
        const uint32_t* Bs = reinterpret_cast<const uint32_t*>(sm + stage * 2 * TILE_F + TILE_F);

        const int arow = wm * 32 + (lane >> 2);
        const int brow = wn * 64 + (lane >> 2);
        const int kl   = lane & 3;

        #pragma unroll
        for (int kk = 0; kk < 4; kk++) {
            const int kc = kk * 8 + kl;
            uint32_t af[2][4], bf[8][2];
            #pragma unroll
            for (int mt = 0; mt < 2; mt++) {
                const int r = arow + mt * 16;
                af[mt][0] = As[r * PADK + kc];
                af[mt][1] = As[(r + 8) * PADK + kc];
                af[mt][2] = As[r * PADK + kc + 4];
                af[mt][3] = As[(r + 8) * PADK + kc + 4];
            }
            #pragma unroll
            for (int nt = 0; nt < 8; nt++) {
                const int r = brow + nt * 8;
                bf[nt][0] = Bs[r * PADK + kc];
                bf[nt][1] = Bs[r * PADK + kc + 4];
            }
            #pragma unroll
            for (int mt = 0; mt < 2; mt++)
                #pragma unroll
                for (int nt = 0; nt < 8; nt++)
                    mma_tf32(acc[mt][nt], af[mt], bf[nt]);
        }
        __syncthreads();
    }

    // Epilogue
    #pragma unroll
    for (int mt = 0; mt < 2; mt++) {
        const int row = m0 + wm * 32 + mt * 16 + (lane >> 2);
        #pragma unroll
        for (int nt = 0; nt < 8; nt++) {
            const int col = n0 + wn * 64 + nt * 8 + (lane & 3) * 2;
            *reinterpret_cast<float2*>(C + (size_t)row * ldc + col) =
                make_float2(acc[mt][nt][0], acc[mt][nt][1]);
            *reinterpret_cast<float2*>(C + (size_t)(row + 8) * ldc + col) =
                make_float2(acc[mt][nt][2], acc[mt][nt][3]);
        }
    }
}

// ---------------------------------------------------------------------------
// fp32 SGEMM (small Q / Out GEMMs)
// ---------------------------------------------------------------------------
__global__ __launch_bounds__(256) void sgemm(
    const float* __restrict__ A, const float* __restrict__ B,
    float* __restrict__ C, int M, int N, int K)
{
    __shared__ float As[16 * 128];
    __shared__ float Bs[16 * 128];

    const int tid = threadIdx.x;
    const int tx = tid & 15;
    const int ty = tid >> 4;
    const int bx = blockIdx.x;
    const int by = blockIdx.y;

    const int aRow = tid >> 2;
    const int aCol = (tid & 3) << 2;
    const int bRow = tid >> 5;
    const int bCol = (tid & 31) << 2;

    const float* Aptr = A + (size_t)by * 128 * K;
    const float* Bptr = B + (size_t)bx * 128;

    float acc[8][8] = {};

    for (int k0 = 0; k0 < K; k0 += 16) {
        #pragma unroll
        for (int p = 0; p < 2; p++) {
            const int r = aRow + p * 64;
            float4 v = *reinterpret_cast<const float4*>(Aptr + (size_t)r * K + k0 + aCol);
            As[(aCol + 0) * 128 + r] = v.x;
            As[(aCol + 1) * 128 + r] = v.y;
            As[(aCol + 2) * 128 + r] = v.z;
            As[(aCol + 3) * 128 + r] = v.w;
        }
        #pragma unroll
        for (int p = 0; p < 2; p++) {
            const int r = bRow + p * 8;
            *reinterpret_cast<float4*>(Bs + r * 128 + bCol) =
                *reinterpret_cast<const float4*>(Bptr + (size_t)(k0 + r) * N + bCol);
        }
        __syncthreads();

        #pragma unroll
        for (int kk = 0; kk < 16; kk++) {
            float a[8], bq[8];
            float4 a0 = *reinterpret_cast<const float4*>(As + kk * 128 + ty * 8);
            float4 a1 = *reinterpret_cast<const float4*>(As + kk * 128 + ty * 8 + 4);
            float4 b0 = *reinterpret_cast<const float4*>(Bs + kk * 128 + tx * 8);
            float4 b1 = *reinterpret_cast<const float4*>(Bs + kk * 128 + tx * 8 + 4);
            a[0]=a0.x; a[1]=a0.y; a[2]=a0.z; a[3]=a0.w;
            a[4]=a1.x; a[5]=a1.y; a[6]=a1.z; a[7]=a1.w;
            bq[0]=b0.x; bq[1]=b0.y; bq[2]=b0.z; bq[3]=b0.w;
            bq[4]=b1.x; bq[5]=b1.y; bq[6]=b1.z; bq[7]=b1.w;
            #pragma unroll
            for (int ii = 0; ii < 8; ii++)
                #pragma unroll
                for (int jj = 0; jj < 8; jj++)
                    acc[ii][jj] += a[ii] * bq[jj];
        }
        __syncthreads();
    }

    float* Cp = C + (size_t)(by * 128 + ty * 8) * N + bx * 128 + tx * 8;
    #pragma unroll
    for (int ii = 0; ii < 8; ii++) {
        float4 o0 = make_float4(acc[ii][0], acc[ii][1], acc[ii][2], acc[ii][3]);
        float4 o1 = make_float4(acc[ii][4], acc[ii][5], acc[ii][6], acc[ii][7]);
        *reinterpret_cast<float4*>(Cp + (size_t)ii * N)     = o0;
        *reinterpret_cast<float4*>(Cp + (size_t)ii * N + 4) = o1;
    }
}

// ---------------------------------------------------------------------------
// Flash attention (unchanged from Round 1)
// ---------------------------------------------------------------------------
__global__ __launch_bounds__(256) void attn_kernel(const float* __restrict__ mask)
{
    __shared__ float qs_t[64 * 64];
    __shared__ float ks_t[64 * 64];
    __shared__ float vs  [64 * 64];

    const int h = blockIdx.x;
    const int b = blockIdx.y;
    const int tid = threadIdx.x;
    const int tq = tid >> 4;
    const int tx = tid & 15;

    {
        const int qr = tid >> 2;
        const int dg = tid & 3;
        const float4* src = reinterpret_cast<const float4*>(
            g_q + ((size_t)(b * N2 + qr)) * DIM + h * DH + dg * 16);
        #pragma unroll
        for (int ii = 0; ii < 4; ii++) {
            float4 v = src[ii];
            const int d0 = dg * 16 + ii * 4;
            qs_t[(d0 + 0) * 64 + qr] = v.x * 0.125f;
            qs_t[(d0 + 1) * 64 + qr] = v.y * 0.125f;
            qs_t[(d0 + 2) * 64 + qr] = v.z * 0.125f;
            qs_t[(d0 + 3) * 64 + qr] = v.w * 0.125f;
        }
    }

    float O[4][4] = {};
    float m[4], l[4];
    #pragma unroll
    for (int i = 0; i < 4; i++) { m[i] = -1e30f; l[i] = 0.f; }

    const size_t kvbase = (size_t)b * NKEYS * (2 * DIM);

    for (int ch = 0; ch < NKEYS / 64; ch++) {
        const int key0 = ch * 64;
        __syncthreads();

        {
            const int kl = tid >> 2;
            const int dg = tid & 3;
            const float4* ksrc = reinterpret_cast<const float4*>(
                g_kv + kvbase + (size_t)(key0 + kl) * (2 * DIM) + h * DH + dg * 16);
            #pragma unroll
            for (int ii = 0; ii < 4; ii++) {
                float4 v = ksrc[ii];
                const int d0 = dg * 16 + ii * 4;
                ks_t[(d0 + 0) * 64 + kl] = v.x;
                ks_t[(d0 + 1) * 64 + kl] = v.y;
                ks_t[(d0 + 2) * 64 + kl] = v.z;
                ks_t[(d0 + 3) * 64 + kl] = v.w;
            }
            const float4* vsrc = reinterpret_cast<const float4*>(
                g_kv + kvbase + (size_t)(key0 + kl) * (2 * DIM) + DIM + h * DH + dg * 16);
            float4* vdst = reinterpret_cast<float4*>(vs + kl * 64 + dg * 16);
            #pragma unroll
            for (int ii = 0; ii < 4; ii++) vdst[ii] = vsrc[ii];
        }
        __syncthreads();

        float acc[4][4] = {};
        #pragma unroll 8
        for (int d = 0; d < 64; d++) {
            float4 av = *reinterpret_cast<const float4*>(qs_t + d * 64 + tq * 4);
            float4 bv = *reinterpret_cast<const float4*>(ks_t + d * 64 + tx * 4);
            float a[4] = {av.x, av.y, av.z, av.w};
            float kb[4] = {bv.x, bv.y, bv.z, bv.w};
            #pragma unroll
            for (int i = 0; i < 4; i++)
                #pragma unroll
                for (int j = 0; j < 4; j++)
                    acc[i][j] += a[i] * kb[j];
        }

        #pragma unroll
        for (int j = 0; j < 4; j++) {
            const int kg = key0 + tx * 4 + j;
            float bias = 0.f;
            if (kg < N1) bias = (mask[(size_t)b * N1 + kg] - 1.0f) * 100.0f;
            #pragma unroll
            for (int i = 0; i < 4; i++) acc[i][j] += bias;
        }

        float alpha[4];
        #pragma unroll
        for (int i = 0; i < 4; i++) {
            float cm = fmaxf(fmaxf(acc[i][0], acc[i][1]), fmaxf(acc[i][2], acc[i][3]));
            #pragma unroll
            for (int o = 1; o < 16; o <<= 1)
                cm = fmaxf(cm, __shfl_xor_sync(0xffffffffu, cm, o));
            const float mn = fmaxf(m[i], cm);
            alpha[i] = __expf(m[i] - mn);
            float cl = 0.f;
            #pragma unroll
            for (int j = 0; j < 4; j++) {
                const float p = __expf(acc[i][j] - mn);
                acc[i][j] = p;
                cl += p;
            }
            #pragma unroll
            for (int o = 1; o < 16; o <<= 1)
                cl += __shfl_xor_sync(0xffffffffu, cl, o);
            l[i] = l[i] * alpha[i] + cl;
            m[i] = mn;
            #pragma unroll
            for (int j = 0; j < 4; j++) O[i][j] *= alpha[i];
        }

        __syncthreads();
        #pragma unroll
        for (int i = 0; i < 4; i++)
            #pragma unroll
            for (int j = 0; j < 4; j++)
                ks_t[(tq * 4 + i) * 64 + tx * 4 + j] = acc[i][j];
        __syncthreads();

        #pragma unroll 8
        for (int k = 0; k < 64; k++) {
            float p0 = ks_t[(tq * 4 + 0) * 64 + k];
            float p1 = ks_t[(tq * 4 + 1) * 64 + k];
            float p2 = ks_t[(tq * 4 + 2) * 64 + k];
            float p3 = ks_t[(tq * 4 + 3) * 64 + k];
            float4 vv = *reinterpret_cast<const float4*>(vs + k * 64 + tx * 4);
            float v4[4] = {vv.x, vv.y, vv.z, vv.w};
            #pragma unroll
            for (int j = 0; j < 4; j++) {
                O[0][j] += p0 * v4[j];
                O[1][j] += p1 * v4[j];
                O[2][j] += p2 * v4[j];
                O[3][j] += p3 * v4[j];
            }
        }
    }

    #pragma unroll
    for (int i = 0; i < 4; i++) {
        const float inv = 1.0f / l[i];
        float4 o = make_float4(O[i][0] * inv, O[i][1] * inv, O[i][2] * inv, O[i][3] * inv);
        *reinterpret_cast<float4*>(
            g_attn + ((size_t)(b * N2 + tq * 4 + i)) * DIM + h * DH + tx * 4) = o;
    }
}

// ---------------------------------------------------------------------------
// Launch
// ---------------------------------------------------------------------------
extern "C" void kernel_launch(void* const* d_in, const int* in_sizes, int n_in,
                              void* d_out, int out_size)
{
    const float* x       = (const float*)d_in[0];
    const float* latents = (const float*)d_in[1];
    const float* mask    = (const float*)d_in[2];
    const float* ln1g    = (const float*)d_in[3];
    const float* ln1b    = (const float*)d_in[4];
    const float* ln2g    = (const float*)d_in[5];
    const float* ln2b    = (const float*)d_in[6];
    const float* Wq      = (const float*)d_in[7];
    const float* Wkv     = (const float*)d_in[8];
    const float* Wout    = (const float*)d_in[9];
    float* out = (float*)d_out;

    float *p_kvin, *p_ln, *p_q, *p_kv, *p_attn, *p_wkvT;
    cudaGetSymbolAddress((void**)&p_kvin, g_kvin);
    cudaGetSymbolAddress((void**)&p_ln,   g_ln);
    cudaGetSymbolAddress((void**)&p_q,    g_q);
    cudaGetSymbolAddress((void**)&p_kv,   g_kv);
    cudaGetSymbolAddress((void**)&p_attn, g_attn);
    cudaGetSymbolAddress((void**)&p_wkvT, g_wkvT);

    static bool attr_set = false;
    if (!attr_set) {
        cudaFuncSetAttribute(gemm_tc, cudaFuncAttributeMaxDynamicSharedMemorySize,
                             GEMM_SMEM_BYTES);
        attr_set = true;
    }

    // 0) Transpose + tf32-round Wkv
    transpose_kernel<<<dim3(2 * DIM / 32, DIM / 32), dim3(32, 8)>>>(Wkv, p_wkvT);

    // 1) LayerNorms (g_kvin tf32-rounded)
    ln_kernel<<<MROWS, 256>>>(x, latents, ln1g, ln1b, ln2g, ln2b);

    // 2) KV GEMM on tensor cores (mma.sync tf32)
    gemm_tc<<<dim3(2 * DIM / 128, MROWS / 128), 256, GEMM_SMEM_BYTES>>>(
        p_kvin, p_wkvT, p_kv, 2 * DIM);

    // 3) Q GEMM (fp32)
    sgemm<<<dim3(DIM / 128, BATCH * N2 / 128), 256>>>(p_ln, Wq, p_q, BATCH * N2, DIM, DIM);

    // 4) Attention
    attn_kernel<<<dim3(HEADS, BATCH), 256>>>(mask);

    // 5) Output GEMM (fp32)
    sgemm<<<dim3(DIM / 128, BATCH * N2 / 128), 256>>>(p_attn, Wout, out, BATCH * N2, DIM, DIM);
}

// round 4
// speedup vs baseline: 2.8753x; 1.2475x over previous
#include <cuda_runtime.h>
#include <cstdint>

// ---------------------------------------------------------------------------
// PerceiverAttention, sm_103 — Round 3:
//   * all three GEMMs on mma.sync tf32 (gemm_tc, 3-stage cp.async pipeline)
//   * split-K flash attention (5 splits) + merge kernel
// ---------------------------------------------------------------------------

#define BATCH 8
#define N1 4096
#define N2 64
#define NKEYS 4160
#define DIM 1024
#define HEADS 16
#define DH 64
#define MROWS (BATCH * NKEYS)   // 33280
#define NSPLIT 5
#define CH_PER_SPLIT 13         // 13 * 64 * 5 = 4160

__device__ float g_kvin[(size_t)MROWS * DIM];
__device__ float g_ln  [(size_t)BATCH * N2 * DIM];
__device__ float g_q   [(size_t)BATCH * N2 * DIM];
__device__ float g_kv  [(size_t)MROWS * 2 * DIM];
__device__ float g_attn[(size_t)BATCH * N2 * DIM];
__device__ float g_wkvT[(size_t)2 * DIM * DIM];
__device__ float g_wqT [(size_t)DIM * DIM];
__device__ float g_woT [(size_t)DIM * DIM];
__device__ float g_pO  [(size_t)BATCH * HEADS * NSPLIT * N2 * DH];   // partial O
__device__ float g_pml [(size_t)BATCH * HEADS * NSPLIT * 2 * N2];    // partial m,l

// ---------------------------------------------------------------------------
// Helpers
// ---------------------------------------------------------------------------
__device__ __forceinline__ uint32_t smem_u32(const void* p) {
    uint32_t a;
    asm("{ .reg .u64 t; cvta.to.shared.u64 t, %1; cvt.u32.u64 %0, t; }" : "=r"(a) : "l"(p));
    return a;
}
__device__ __forceinline__ float f2tf32(float f) {
    uint32_t r;
    asm("cvt.rna.tf32.f32 %0, %1;" : "=r"(r) : "f"(f));
    return __uint_as_float(r);
}
__device__ __forceinline__ void cp_async16(uint32_t dst, const void* src) {
    asm volatile("cp.async.cg.shared.global [%0], [%1], 16;" :: "r"(dst), "l"(src));
}
__device__ __forceinline__ void cp_commit() {
    asm volatile("cp.async.commit_group;" ::: "memory");
}
template <int N>
__device__ __forceinline__ void cp_wait() {
    asm volatile("cp.async.wait_group %0;" :: "n"(N) : "memory");
}
__device__ __forceinline__ void mma_tf32(float* d, const uint32_t* a, const uint32_t* b) {
    asm volatile(
        "mma.sync.aligned.m16n8k8.row.col.f32.tf32.tf32.f32 "
        "{%0,%1,%2,%3}, {%4,%5,%6,%7}, {%8,%9}, {%0,%1,%2,%3};"
        : "+f"(d[0]), "+f"(d[1]), "+f"(d[2]), "+f"(d[3])
        : "r"(a[0]), "r"(a[1]), "r"(a[2]), "r"(a[3]), "r"(b[0]), "r"(b[1]));
}

// ---------------------------------------------------------------------------
// Transpose + tf32-round: in (DIM rows x ncols) -> out (ncols x DIM)
// ---------------------------------------------------------------------------
__global__ __launch_bounds__(256) void transpose_kernel(
    const float* __restrict__ in, float* __restrict__ out, int ncols)
{
    __shared__ float t[32][33];
    const int bx = blockIdx.x * 32;   // n
    const int by = blockIdx.y * 32;   // k
    const int x = threadIdx.x;
    const int y = threadIdx.y;
    #pragma unroll
    for (int i = 0; i < 32; i += 8)
        t[y + i][x] = f2tf32(in[(size_t)(by + y + i) * ncols + bx + x]);
    __syncthreads();
    #pragma unroll
    for (int i = 0; i < 32; i += 8)
        out[(size_t)(bx + y + i) * DIM + by + x] = t[x][y + i];
}

// ---------------------------------------------------------------------------
// LayerNorm: g_kvin AND g_ln get tf32-rounded outputs (both feed tf32 GEMMs)
// ---------------------------------------------------------------------------
__global__ __launch_bounds__(256) void ln_kernel(
    const float* __restrict__ x, const float* __restrict__ lat,
    const float* __restrict__ g1, const float* __restrict__ b1,
    const float* __restrict__ g2, const float* __restrict__ b2)
{
    __shared__ float red[16];
    const int r  = blockIdx.x;
    const int bb = r / NKEYS;
    const int i  = r - bb * NKEYS;

    const float* src;
    const float* g;
    const float* be;
    float* dst2 = nullptr;
    if (i < N1) {
        src = x + ((size_t)bb * N1 + i) * DIM;
        g = g1; be = b1;
    } else {
        const int j = i - N1;
        src = lat + ((size_t)bb * N2 + j) * DIM;
        g = g2; be = b2;
        dst2 = g_ln + ((size_t)bb * N2 + j) * DIM;
    }
    float* dst = g_kvin + (size_t)r * DIM;

    const int t = threadIdx.x;
    float4 v = reinterpret_cast<const float4*>(src)[t];
    float s  = v.x + v.y + v.z + v.w;
    float sq = v.x * v.x + v.y * v.y + v.z * v.z + v.w * v.w;
    #pragma unroll
    for (int o = 16; o > 0; o >>= 1) {
        s  += __shfl_xor_sync(0xffffffffu, s, o);
        sq += __shfl_xor_sync(0xffffffffu, sq, o);
    }
    if ((t & 31) == 0) { red[t >> 5] = s; red[8 + (t >> 5)] = sq; }
    __syncthreads();
    float S = 0.f, SQ = 0.f;
    #pragma unroll
    for (int k = 0; k < 8; k++) { S += red[k]; SQ += red[8 + k]; }

    const float mu   = S * (1.0f / DIM);
    const float var  = SQ * (1.0f / DIM) - mu * mu;
    const float rstd = rsqrtf(var + 1e-5f);

    float4 gv = reinterpret_cast<const float4*>(g)[t];
    float4 bv = reinterpret_cast<const float4*>(be)[t];
    float4 o;
    o.x = f2tf32((v.x - mu) * rstd * gv.x + bv.x);
    o.y = f2tf32((v.y - mu) * rstd * gv.y + bv.y);
    o.z = f2tf32((v.z - mu) * rstd * gv.z + bv.z);
    o.w = f2tf32((v.w - mu) * rstd * gv.w + bv.w);
    reinterpret_cast<float4*>(dst)[t] = o;
    if (dst2) reinterpret_cast<float4*>(dst2)[t] = o;
}

// ---------------------------------------------------------------------------
// tf32 mma.sync GEMM, 3-stage cp.async pipeline.
// C[M x N] = A[M x 1024] @ Bt[N x 1024]^T, tiles 128x128, K-chunk 32.
// ---------------------------------------------------------------------------
#define PADK 36
#define TILE_F (128 * PADK)
#define NSTAGE 3
#define GEMM_SMEM_BYTES (NSTAGE * 2 * TILE_F * 4)   // 110592

__global__ __launch_bounds__(256, 2) void gemm_tc(
    const float* __restrict__ A, const float* __restrict__ Bt,
    float* __restrict__ C, int ldc)
{
    extern __shared__ float sm[];
    const uint32_t sb = smem_u32(sm);

    const int tid  = threadIdx.x;
    const int wid  = tid >> 5;
    const int lane = tid & 31;
    const int wm = wid & 3;
    const int wn = wid >> 2;
    const int m0 = blockIdx.y * 128;
    const int n0 = blockIdx.x * 128;

    const float* ga = A  + (size_t)m0 * DIM;
    const float* gb = Bt + (size_t)n0 * DIM;

    const int lr = tid >> 3;
    const int lc = tid & 7;

    float acc[2][8][4];
    #pragma unroll
    for (int i = 0; i < 2; i++)
        #pragma unroll
        for (int j = 0; j < 8; j++)
            #pragma unroll
            for (int q = 0; q < 4; q++) acc[i][j][q] = 0.f;

    auto load_tile = [&](int chunk, int stage) {
        const uint32_t abase = sb + (uint32_t)stage * 2 * TILE_F * 4;
        const uint32_t bbase = abase + TILE_F * 4;
        const int k0 = chunk * 32;
        #pragma unroll
        for (int i = 0; i < 4; i++) {
            const int r = lr + i * 32;
            cp_async16(abase + (r * PADK + lc * 4) * 4, ga + (size_t)r * DIM + k0 + lc * 4);
        }
        #pragma unroll
        for (int i = 0; i < 4; i++) {
            const int r = lr + i * 32;
            cp_async16(bbase + (r * PADK + lc * 4) * 4, gb + (size_t)r * DIM + k0 + lc * 4);
        }
        cp_commit();
    };

    const int NCHUNK = DIM / 32;   // 32
    load_tile(0, 0);
    load_tile(1, 1);

    for (int c = 0; c < NCHUNK; c++) {
        const int stage = c % NSTAGE;
        if (c + 2 < NCHUNK) { load_tile(c + 2, (c + 2) % NSTAGE); cp_wait<2>(); }
        else if (c + 2 == NCHUNK) { cp_wait<1>(); }
        else { cp_wait<0>(); }
        __syncthreads();

        const uint32_t* As = reinterpret_cast<const uint32_t*>(sm + stage * 2 * TILE_F);
        const uint32_t* Bs = reinterpret_cast<const uint32_t*>(sm + stage * 2 * TILE_F + TILE_F);

        const int arow = wm * 32 + (lane >> 2);
        const int brow = wn * 64 + (lane >> 2);
        const int kl   = lane & 3;

        #pragma unroll
        for (int kk = 0; kk < 4; kk++) {
            const int kc = kk * 8 + kl;
            uint32_t af[2][4], bf[8][2];
            #pragma unroll
            for (int mt = 0; mt < 2; mt++) {
                const int r = arow + mt * 16;
                af[mt][0] = As[r * PADK + kc];
                af[mt][1] = As[(r + 8) * PADK + kc];
                af[mt][2] = As[r * PADK + kc + 4];
                af[mt][3] = As[(r + 8) * PADK + kc + 4];
            }
            #pragma unroll
            for (int nt = 0; nt < 8; nt++) {
                const int r = brow + nt * 8;
                bf[nt][0] = Bs[r * PADK + kc];
                bf[nt][1] = Bs[r * PADK + kc + 4];
            }
            #pragma unroll
            for (int mt = 0; mt < 2; mt++)
                #pragma unroll
                for (int nt = 0; nt < 8; nt++)
                    mma_tf32(acc[mt][nt], af[mt], bf[nt]);
        }
        __syncthreads();
    }

    #pragma unroll
    for (int mt = 0; mt < 2; mt++) {
        const int row = m0 + wm * 32 + mt * 16 + (lane >> 2);
        #pragma unroll
        for (int nt = 0; nt < 8; nt++) {
            const int col = n0 + wn * 64 + nt * 8 + (lane & 3) * 2;
            *reinterpret_cast<float2*>(C + (size_t)row * ldc + col) =
                make_float2(acc[mt][nt][0], acc[mt][nt][1]);
            *reinterpret_cast<float2*>(C + (size_t)(row + 8) * ldc + col) =
                make_float2(acc[mt][nt][2], acc[mt][nt][3]);
        }
    }
}

// ---------------------------------------------------------------------------
// Split-K flash attention: grid (HEADS, BATCH, NSPLIT); each block processes
// 13 chunks of 64 keys and writes unnormalized partial O + (m, l).
// ---------------------------------------------------------------------------
__global__ __launch_bounds__(256) void attn_partial(const float* __restrict__ mask)
{
    __shared__ float qs_t[64 * 64];
    __shared__ float ks_t[64 * 64];
    __shared__ float vs  [64 * 64];

    const int h = blockIdx.x;
    const int b = blockIdx.y;
    const int sp = blockIdx.z;
    const int bh = b * HEADS + h;
    const int tid = threadIdx.x;
    const int tq = tid >> 4;
    const int tx = tid & 15;

    {
        const int qr = tid >> 2;
        const int dg = tid & 3;
        const float4* src = reinterpret_cast<const float4*>(
            g_q + ((size_t)(b * N2 + qr)) * DIM + h * DH + dg * 16);
        #pragma unroll
        for (int ii = 0; ii < 4; ii++) {
            float4 v = src[ii];
            const int d0 = dg * 16 + ii * 4;
            qs_t[(d0 + 0) * 64 + qr] = v.x * 0.125f;
            qs_t[(d0 + 1) * 64 + qr] = v.y * 0.125f;
            qs_t[(d0 + 2) * 64 + qr] = v.z * 0.125f;
            qs_t[(d0 + 3) * 64 + qr] = v.w * 0.125f;
        }
    }

    float O[4][4] = {};
    float m[4], l[4];
    #pragma unroll
    for (int i = 0; i < 4; i++) { m[i] = -1e30f; l[i] = 0.f; }

    const size_t kvbase = (size_t)b * NKEYS * (2 * DIM);

    for (int cc = 0; cc < CH_PER_SPLIT; cc++) {
        const int key0 = (sp * CH_PER_SPLIT + cc) * 64;
        __syncthreads();

        {
            const int kl = tid >> 2;
            const int dg = tid & 3;
            const float4* ksrc = reinterpret_cast<const float4*>(
                g_kv + kvbase + (size_t)(key0 + kl) * (2 * DIM) + h * DH + dg * 16);
            #pragma unroll
            for (int ii = 0; ii < 4; ii++) {
                float4 v = ksrc[ii];
                const int d0 = dg * 16 + ii * 4;
                ks_t[(d0 + 0) * 64 + kl] = v.x;
                ks_t[(d0 + 1) * 64 + kl] = v.y;
                ks_t[(d0 + 2) * 64 + kl] = v.z;
                ks_t[(d0 + 3) * 64 + kl] = v.w;
            }
            const float4* vsrc = reinterpret_cast<const float4*>(
                g_kv + kvbase + (size_t)(key0 + kl) * (2 * DIM) + DIM + h * DH + dg * 16);
            float4* vdst = reinterpret_cast<float4*>(vs + kl * 64 + dg * 16);
            #pragma unroll
            for (int ii = 0; ii < 4; ii++) vdst[ii] = vsrc[ii];
        }
        __syncthreads();

        float acc[4][4] = {};
        #pragma unroll 8
        for (int d = 0; d < 64; d++) {
            float4 av = *reinterpret_cast<const float4*>(qs_t + d * 64 + tq * 4);
            float4 bv = *reinterpret_cast<const float4*>(ks_t + d * 64 + tx * 4);
            float a[4] = {av.x, av.y, av.z, av.w};
            float kb[4] = {bv.x, bv.y, bv.z, bv.w};
            #pragma unroll
            for (int i = 0; i < 4; i++)
                #pragma unroll
                for (int j = 0; j < 4; j++)
                    acc[i][j] += a[i] * kb[j];
        }

        #pragma unroll
        for (int j = 0; j < 4; j++) {
            const int kg = key0 + tx * 4 + j;
            float bias = 0.f;
            if (kg < N1) bias = (mask[(size_t)b * N1 + kg] - 1.0f) * 100.0f;
            #pragma unroll
            for (int i = 0; i < 4; i++) acc[i][j] += bias;
        }

        float alpha[4];
        #pragma unroll
        for (int i = 0; i < 4; i++) {
            float cm = fmaxf(fmaxf(acc[i][0], acc[i][1]), fmaxf(acc[i][2], acc[i][3]));
            #pragma unroll
            for (int o = 1; o < 16; o <<= 1)
                cm = fmaxf(cm, __shfl_xor_sync(0xffffffffu, cm, o));
            const float mn = fmaxf(m[i], cm);
            alpha[i] = __expf(m[i] - mn);
            float cl = 0.f;
            #pragma unroll
            for (int j = 0; j < 4; j++) {
                const float p = __expf(acc[i][j] - mn);
                acc[i][j] = p;
                cl += p;
            }
            #pragma unroll
            for (int o = 1; o < 16; o <<= 1)
                cl += __shfl_xor_sync(0xffffffffu, cl, o);
            l[i] = l[i] * alpha[i] + cl;
            m[i] = mn;
            #pragma unroll
            for (int j = 0; j < 4; j++) O[i][j] *= alpha[i];
        }

        __syncthreads();
        #pragma unroll
        for (int i = 0; i < 4; i++)
            #pragma unroll
            for (int j = 0; j < 4; j++)
                ks_t[(tq * 4 + i) * 64 + tx * 4 + j] = acc[i][j];
        __syncthreads();

        #pragma unroll 8
        for (int k = 0; k < 64; k++) {
            float p0 = ks_t[(tq * 4 + 0) * 64 + k];
            float p1 = ks_t[(tq * 4 + 1) * 64 + k];
            float p2 = ks_t[(tq * 4 + 2) * 64 + k];
            float p3 = ks_t[(tq * 4 + 3) * 64 + k];
            float4 vv = *reinterpret_cast<const float4*>(vs + k * 64 + tx * 4);
            float v4[4] = {vv.x, vv.y, vv.z, vv.w};
            #pragma unroll
            for (int j = 0; j < 4; j++) {
                O[0][j] += p0 * v4[j];
                O[1][j] += p1 * v4[j];
                O[2][j] += p2 * v4[j];
                O[3][j] += p3 * v4[j];
            }
        }
    }

    // Write unnormalized partial O and (m, l)
    float* po = g_pO + ((size_t)(bh * NSPLIT + sp) * N2) * DH;
    #pragma unroll
    for (int i = 0; i < 4; i++) {
        *reinterpret_cast<float4*>(po + (size_t)(tq * 4 + i) * DH + tx * 4) =
            make_float4(O[i][0], O[i][1], O[i][2], O[i][3]);
    }
    if (tx == 0) {
        float* pml = g_pml + (size_t)(bh * NSPLIT + sp) * 2 * N2;
        #pragma unroll
        for (int i = 0; i < 4; i++) {
            pml[tq * 4 + i]      = m[i];
            pml[N2 + tq * 4 + i] = l[i];
        }
    }
}

// ---------------------------------------------------------------------------
// Merge partials -> g_attn (tf32-rounded; feeds tf32 Out GEMM)
// Block per (b,h), 256 threads: q = tid>>2, 16 d-values per thread.
// ---------------------------------------------------------------------------
__global__ __launch_bounds__(256) void attn_merge()
{
    const int bh = blockIdx.x;
    const int b = bh / HEADS;
    const int h = bh - b * HEADS;
    const int tid = threadIdx.x;
    const int q  = tid >> 2;
    const int dq = tid & 3;     // covers d = dq*16 .. dq*16+15

    float ms[NSPLIT], ls[NSPLIT];
    float M = -1e30f;
    #pragma unroll
    for (int s = 0; s < NSPLIT; s++) {
        const float* pml = g_pml + (size_t)(bh * NSPLIT + s) * 2 * N2;
        ms[s] = pml[q];
        ls[s] = pml[N2 + q];
        M = fmaxf(M, ms[s]);
    }
    float w[NSPLIT], lt = 0.f;
    #pragma unroll
    for (int s = 0; s < NSPLIT; s++) {
        w[s] = __expf(ms[s] - M);
        lt += ls[s] * w[s];
    }
    const float inv = 1.0f / lt;

    float* dst = g_attn + ((size_t)(b * N2 + q)) * DIM + h * DH + dq * 16;
    #pragma unroll
    for (int j = 0; j < 4; j++) {
        float4 acc = make_float4(0.f, 0.f, 0.f, 0.f);
        #pragma unroll
        for (int s = 0; s < NSPLIT; s++) {
            const float4 v = *reinterpret_cast<const float4*>(
                g_pO + ((size_t)(bh * NSPLIT + s) * N2 + q) * DH + dq * 16 + j * 4);
            acc.x += w[s] * v.x;
            acc.y += w[s] * v.y;
            acc.z += w[s] * v.z;
            acc.w += w[s] * v.w;
        }
        *reinterpret_cast<float4*>(dst + j * 4) =
            make_float4(f2tf32(acc.x * inv), f2tf32(acc.y * inv),
                        f2tf32(acc.z * inv), f2tf32(acc.w * inv));
    }
}

// ---------------------------------------------------------------------------
// Launch
// ---------------------------------------------------------------------------
extern "C" void kernel_launch(void* const* d_in, const int* in_sizes, int n_in,
                              void* d_out, int out_size)
{
    const float* x       = (const float*)d_in[0];
    const float* latents = (const float*)d_in[1];
    const float* mask    = (const float*)d_in[2];
    const float* ln1g    = (const float*)d_in[3];
    const float* ln1b    = (const float*)d_in[4];
    const float* ln2g    = (const float*)d_in[5];
    const float* ln2b    = (const float*)d_in[6];
    const float* Wq      = (const float*)d_in[7];
    const float* Wkv     = (const float*)d_in[8];
    const float* Wout    = (const float*)d_in[9];
    float* out = (float*)d_out;

    float *p_kvin, *p_ln, *p_q, *p_kv, *p_attn, *p_wkvT, *p_wqT, *p_woT;
    cudaGetSymbolAddress((void**)&p_kvin, g_kvin);
    cudaGetSymbolAddress((void**)&p_ln,   g_ln);
    cudaGetSymbolAddress((void**)&p_q,    g_q);
    cudaGetSymbolAddress((void**)&p_kv,   g_kv);
    cudaGetSymbolAddress((void**)&p_attn, g_attn);
    cudaGetSymbolAddress((void**)&p_wkvT, g_wkvT);
    cudaGetSymbolAddress((void**)&p_wqT,  g_wqT);
    cudaGetSymbolAddress((void**)&p_woT,  g_woT);

    static bool attr_set = false;
    if (!attr_set) {
        cudaFuncSetAttribute(gemm_tc, cudaFuncAttributeMaxDynamicSharedMemorySize,
                             GEMM_SMEM_BYTES);
        attr_set = true;
    }

    // 0) Transpose + tf32-round all weights
    transpose_kernel<<<dim3(2 * DIM / 32, DIM / 32), dim3(32, 8)>>>(Wkv, p_wkvT, 2 * DIM);
    transpose_kernel<<<dim3(DIM / 32, DIM / 32), dim3(32, 8)>>>(Wq, p_wqT, DIM);
    transpose_kernel<<<dim3(DIM / 32, DIM / 32), dim3(32, 8)>>>(Wout, p_woT, DIM);

    // 1) LayerNorms (outputs tf32-rounded)
    ln_kernel<<<MROWS, 256>>>(x, latents, ln1g, ln1b, ln2g, ln2b);

    // 2) KV GEMM (tf32 mma): (33280 x 1024) @ (1024 x 2048)
    gemm_tc<<<dim3(2 * DIM / 128, MROWS / 128), 256, GEMM_SMEM_BYTES>>>(
        p_kvin, p_wkvT, p_kv, 2 * DIM);

    // 3) Q GEMM (tf32 mma): (512 x 1024) @ (1024 x 1024)
    gemm_tc<<<dim3(DIM / 128, BATCH * N2 / 128), 256, GEMM_SMEM_BYTES>>>(
        p_ln, p_wqT, p_q, DIM);

    // 4) Attention: split-K partials + merge
    attn_partial<<<dim3(HEADS, BATCH, NSPLIT), 256>>>(mask);
    attn_merge<<<BATCH * HEADS, 256>>>();

    // 5) Out GEMM (tf32 mma): (512 x 1024) @ (1024 x 1024) -> d_out
    gemm_tc<<<dim3(DIM / 128, BATCH * N2 / 128), 256, GEMM_SMEM_BYTES>>>(
        p_attn, p_woT, out, DIM);
}

// round 5
// speedup vs baseline: 4.3108x; 1.4992x over previous
#include <cuda_runtime.h>
#include <cuda_fp16.h>
#include <cstdint>

// ---------------------------------------------------------------------------
// PerceiverAttention, sm_103 — Round 4:
//   * all three GEMMs on mma.sync fp16 (m16n8k16), fp32 accumulate
//   * operands stored as __half (producers round with __float2half_rn)
//   * split-K flash attention (5 splits, fp32) + merge
// ---------------------------------------------------------------------------

#define BATCH 8
#define N1 4096
#define N2 64
#define NKEYS 4160
#define DIM 1024
#define HEADS 16
#define DH 64
#define MROWS (BATCH * NKEYS)   // 33280
#define NSPLIT 5
#define CH_PER_SPLIT 13

__device__ __half g_kvin[(size_t)MROWS * DIM];        // LN(x)++LN(lat), half
__device__ __half g_lnh [(size_t)BATCH * N2 * DIM];   // LN(latents), half
__device__ float  g_q   [(size_t)BATCH * N2 * DIM];
__device__ float  g_kv  [(size_t)MROWS * 2 * DIM];
__device__ __half g_attnh[(size_t)BATCH * N2 * DIM];  // merged attention, half
__device__ __half g_wkvT[(size_t)2 * DIM * DIM];
__device__ __half g_wqT [(size_t)DIM * DIM];
__device__ __half g_woT [(size_t)DIM * DIM];
__device__ float  g_pO  [(size_t)BATCH * HEADS * NSPLIT * N2 * DH];
__device__ float  g_pml [(size_t)BATCH * HEADS * NSPLIT * 2 * N2];

// ---------------------------------------------------------------------------
// Helpers
// ---------------------------------------------------------------------------
__device__ __forceinline__ uint32_t smem_u32(const void* p) {
    uint32_t a;
    asm("{ .reg .u64 t; cvta.to.shared.u64 t, %1; cvt.u32.u64 %0, t; }" : "=r"(a) : "l"(p));
    return a;
}
__device__ __forceinline__ void cp_async16(uint32_t dst, const void* src) {
    asm volatile("cp.async.cg.shared.global [%0], [%1], 16;" :: "r"(dst), "l"(src));
}
__device__ __forceinline__ void cp_commit() {
    asm volatile("cp.async.commit_group;" ::: "memory");
}
template <int N>
__device__ __forceinline__ void cp_wait() {
    asm volatile("cp.async.wait_group %0;" :: "n"(N) : "memory");
}
__device__ __forceinline__ void mma_f16(float* d, const uint32_t* a, const uint32_t* b) {
    asm volatile(
        "mma.sync.aligned.m16n8k16.row.col.f32.f16.f16.f32 "
        "{%0,%1,%2,%3}, {%4,%5,%6,%7}, {%8,%9}, {%0,%1,%2,%3};"
        : "+f"(d[0]), "+f"(d[1]), "+f"(d[2]), "+f"(d[3])
        : "r"(a[0]), "r"(a[1]), "r"(a[2]), "r"(a[3]), "r"(b[0]), "r"(b[1]));
}

// ---------------------------------------------------------------------------
// Weight transpose + fp16 round: in (DIM rows x ncols) -> out (ncols x DIM)
// ---------------------------------------------------------------------------
__global__ __launch_bounds__(256) void transpose_kernel(
    const float* __restrict__ in, __half* __restrict__ out, int ncols)
{
    __shared__ float t[32][33];
    const int bx = blockIdx.x * 32;   // n
    const int by = blockIdx.y * 32;   // k
    const int x = threadIdx.x;
    const int y = threadIdx.y;
    #pragma unroll
    for (int i = 0; i < 32; i += 8)
        t[y + i][x] = in[(size_t)(by + y + i) * ncols + bx + x];
    __syncthreads();
    #pragma unroll
    for (int i = 0; i < 32; i += 8)
        out[(size_t)(bx + y + i) * DIM + by + x] = __float2half_rn(t[x][y + i]);
}

// ---------------------------------------------------------------------------
// LayerNorm -> half outputs (g_kvin, g_lnh)
// ---------------------------------------------------------------------------
__global__ __launch_bounds__(256) void ln_kernel(
    const float* __restrict__ x, const float* __restrict__ lat,
    const float* __restrict__ g1, const float* __restrict__ b1,
    const float* __restrict__ g2, const float* __restrict__ b2)
{
    __shared__ float red[16];
    const int r  = blockIdx.x;
    const int bb = r / NKEYS;
    const int i  = r - bb * NKEYS;

    const float* src;
    const float* g;
    const float* be;
    __half* dst2 = nullptr;
    if (i < N1) {
        src = x + ((size_t)bb * N1 + i) * DIM;
        g = g1; be = b1;
    } else {
        const int j = i - N1;
        src = lat + ((size_t)bb * N2 + j) * DIM;
        g = g2; be = b2;
        dst2 = g_lnh + ((size_t)bb * N2 + j) * DIM;
    }
    __half* dst = g_kvin + (size_t)r * DIM;

    const int t = threadIdx.x;
    float4 v = reinterpret_cast<const float4*>(src)[t];
    float s  = v.x + v.y + v.z + v.w;
    float sq = v.x * v.x + v.y * v.y + v.z * v.z + v.w * v.w;
    #pragma unroll
    for (int o = 16; o > 0; o >>= 1) {
        s  += __shfl_xor_sync(0xffffffffu, s, o);
        sq += __shfl_xor_sync(0xffffffffu, sq, o);
    }
    if ((t & 31) == 0) { red[t >> 5] = s; red[8 + (t >> 5)] = sq; }
    __syncthreads();
    float S = 0.f, SQ = 0.f;
    #pragma unroll
    for (int k = 0; k < 8; k++) { S += red[k]; SQ += red[8 + k]; }

    const float mu   = S * (1.0f / DIM);
    const float var  = SQ * (1.0f / DIM) - mu * mu;
    const float rstd = rsqrtf(var + 1e-5f);

    float4 gv = reinterpret_cast<const float4*>(g)[t];
    float4 bv = reinterpret_cast<const float4*>(be)[t];
    __half2 h0 = make_half2(__float2half_rn((v.x - mu) * rstd * gv.x + bv.x),
                            __float2half_rn((v.y - mu) * rstd * gv.y + bv.y));
    __half2 h1 = make_half2(__float2half_rn((v.z - mu) * rstd * gv.z + bv.z),
                            __float2half_rn((v.w - mu) * rstd * gv.w + bv.w));
    reinterpret_cast<__half2*>(dst)[t * 2]     = h0;
    reinterpret_cast<__half2*>(dst)[t * 2 + 1] = h1;
    if (dst2) {
        reinterpret_cast<__half2*>(dst2)[t * 2]     = h0;
        reinterpret_cast<__half2*>(dst2)[t * 2 + 1] = h1;
    }
}

// ---------------------------------------------------------------------------
// fp16 mma.sync GEMM, 3-stage cp.async pipeline.
// C[M x N] = A[M x 1024] @ Bt[N x 1024]^T, CTA tile 128x128, K-chunk 64 halves.
// ---------------------------------------------------------------------------
#define PADH 72                         // halves per smem row (64 + 8 pad)
#define TILE_H (128 * PADH)             // halves per stage tile
#define NSTAGE 3
#define GEMM_SMEM_BYTES (NSTAGE * 2 * TILE_H * 2)   // 110592

__global__ __launch_bounds__(256, 2) void gemm_tc(
    const __half* __restrict__ A, const __half* __restrict__ Bt,
    float* __restrict__ C, int ldc)
{
    extern __shared__ __half smh[];
    const uint32_t sb = smem_u32(smh);

    const int tid  = threadIdx.x;
    const int wid  = tid >> 5;
    const int lane = tid & 31;
    const int wm = wid & 3;
    const int wn = wid >> 2;
    const int m0 = blockIdx.y * 128;
    const int n0 = blockIdx.x * 128;

    const __half* ga = A  + (size_t)m0 * DIM;
    const __half* gb = Bt + (size_t)n0 * DIM;

    const int lr = tid >> 3;       // 0..31
    const int lc = tid & 7;        // 16B chunk (8 halves)

    float acc[2][8][4];
    #pragma unroll
    for (int i = 0; i < 2; i++)
        #pragma unroll
        for (int j = 0; j < 8; j++)
            #pragma unroll
            for (int q = 0; q < 4; q++) acc[i][j][q] = 0.f;

    auto load_tile = [&](int chunk, int stage) {
        const uint32_t abase = sb + (uint32_t)stage * 2 * TILE_H * 2;
        const uint32_t bbase = abase + TILE_H * 2;
        const int k0 = chunk * 64;
        #pragma unroll
        for (int i = 0; i < 4; i++) {
            const int r = lr + i * 32;
            cp_async16(abase + (r * PADH + lc * 8) * 2, ga + (size_t)r * DIM + k0 + lc * 8);
        }
        #pragma unroll
        for (int i = 0; i < 4; i++) {
            const int r = lr + i * 32;
            cp_async16(bbase + (r * PADH + lc * 8) * 2, gb + (size_t)r * DIM + k0 + lc * 8);
        }
        cp_commit();
    };

    const int NCHUNK = DIM / 64;   // 16
    load_tile(0, 0);
    load_tile(1, 1);

    for (int c = 0; c < NCHUNK; c++) {
        const int stage = c % NSTAGE;
        if (c + 2 < NCHUNK) { load_tile(c + 2, (c + 2) % NSTAGE); cp_wait<2>(); }
        else if (c + 2 == NCHUNK) { cp_wait<1>(); }
        else { cp_wait<0>(); }
        __syncthreads();

        // u32 views: row stride PADH/2 = 36 u32
        const uint32_t* As = reinterpret_cast<const uint32_t*>(smh + stage * 2 * TILE_H);
        const uint32_t* Bs = reinterpret_cast<const uint32_t*>(smh + stage * 2 * TILE_H + TILE_H);

        const int arow = wm * 32 + (lane >> 2);
        const int brow = wn * 64 + (lane >> 2);
        const int kl   = lane & 3;

        #pragma unroll
        for (int kk = 0; kk < 4; kk++) {          // k-step of 16 halves
            const int kc = kk * 8 + kl;           // u32 column
            uint32_t af[2][4], bf[8][2];
            #pragma unroll
            for (int mt = 0; mt < 2; mt++) {
                const int r = arow + mt * 16;
                af[mt][0] = As[r * 36 + kc];
                af[mt][1] = As[(r + 8) * 36 + kc];
                af[mt][2] = As[r * 36 + kc + 4];
                af[mt][3] = As[(r + 8) * 36 + kc + 4];
            }
            #pragma unroll
            for (int nt = 0; nt < 8; nt++) {
                const int r = brow + nt * 8;
                bf[nt][0] = Bs[r * 36 + kc];
                bf[nt][1] = Bs[r * 36 + kc + 4];
            }
            #pragma unroll
            for (int mt = 0; mt < 2; mt++)
                #pragma unroll
                for (int nt = 0; nt < 8; nt++)
                    mma_f16(acc[mt][nt], af[mt], bf[nt]);
        }
        __syncthreads();
    }

    #pragma unroll
    for (int mt = 0; mt < 2; mt++) {
        const int row = m0 + wm * 32 + mt * 16 + (lane >> 2);
        #pragma unroll
        for (int nt = 0; nt < 8; nt++) {
            const int col = n0 + wn * 64 + nt * 8 + (lane & 3) * 2;
            *reinterpret_cast<float2*>(C + (size_t)row * ldc + col) =
                make_float2(acc[mt][nt][0], acc[mt][nt][1]);
            *reinterpret_cast<float2*>(C + (size_t)(row + 8) * ldc + col) =
                make_float2(acc[mt][nt][2], acc[mt][nt][3]);
        }
    }
}

// ---------------------------------------------------------------------------
// Split-K flash attention (fp32), unchanged from Round 3
// ---------------------------------------------------------------------------
__global__ __launch_bounds__(256) void attn_partial(const float* __restrict__ mask)
{
    __shared__ float qs_t[64 * 64];
    __shared__ float ks_t[64 * 64];
    __shared__ float vs  [64 * 64];

    const int h = blockIdx.x;
    const int b = blockIdx.y;
    const int sp = blockIdx.z;
    const int bh = b * HEADS + h;
    const int tid = threadIdx.x;
    const int tq = tid >> 4;
    const int tx = tid & 15;

    {
        const int qr = tid >> 2;
        const int dg = tid & 3;
        const float4* src = reinterpret_cast<const float4*>(
            g_q + ((size_t)(b * N2 + qr)) * DIM + h * DH + dg * 16);
        #pragma unroll
        for (int ii = 0; ii < 4; ii++) {
            float4 v = src[ii];
            const int d0 = dg * 16 + ii * 4;
            qs_t[(d0 + 0) * 64 + qr] = v.x * 0.125f;
            qs_t[(d0 + 1) * 64 + qr] = v.y * 0.125f;
            qs_t[(d0 + 2) * 64 + qr] = v.z * 0.125f;
            qs_t[(d0 + 3) * 64 + qr] = v.w * 0.125f;
        }
    }

    float O[4][4] = {};
    float m[4], l[4];
    #pragma unroll
    for (int i = 0; i < 4; i++) { m[i] = -1e30f; l[i] = 0.f; }

    const size_t kvbase = (size_t)b * NKEYS * (2 * DIM);

    for (int cc = 0; cc < CH_PER_SPLIT; cc++) {
        const int key0 = (sp * CH_PER_SPLIT + cc) * 64;
        __syncthreads();

        {
            const int kl = tid >> 2;
            const int dg = tid & 3;
            const float4* ksrc = reinterpret_cast<const float4*>(
                g_kv + kvbase + (size_t)(key0 + kl) * (2 * DIM) + h * DH + dg * 16);
            #pragma unroll
            for (int ii = 0; ii < 4; ii++) {
                float4 v = ksrc[ii];
                const int d0 = dg * 16 + ii * 4;
                ks_t[(d0 + 0) * 64 + kl] = v.x;
                ks_t[(d0 + 1) * 64 + kl] = v.y;
                ks_t[(d0 + 2) * 64 + kl] = v.z;
                ks_t[(d0 + 3) * 64 + kl] = v.w;
            }
            const float4* vsrc = reinterpret_cast<const float4*>(
                g_kv + kvbase + (size_t)(key0 + kl) * (2 * DIM) + DIM + h * DH + dg * 16);
            float4* vdst = reinterpret_cast<float4*>(vs + kl * 64 + dg * 16);
            #pragma unroll
            for (int ii = 0; ii < 4; ii++) vdst[ii] = vsrc[ii];
        }
        __syncthreads();

        float acc[4][4] = {};
        #pragma unroll 8
        for (int d = 0; d < 64; d++) {
            float4 av = *reinterpret_cast<const float4*>(qs_t + d * 64 + tq * 4);
            float4 bv = *reinterpret_cast<const float4*>(ks_t + d * 64 + tx * 4);
            float a[4] = {av.x, av.y, av.z, av.w};
            float kb[4] = {bv.x, bv.y, bv.z, bv.w};
            #pragma unroll
            for (int i = 0; i < 4; i++)
                #pragma unroll
                for (int j = 0; j < 4; j++)
                    acc[i][j] += a[i] * kb[j];
        }

        #pragma unroll
        for (int j = 0; j < 4; j++) {
            const int kg = key0 + tx * 4 + j;
            float bias = 0.f;
            if (kg < N1) bias = (mask[(size_t)b * N1 + kg] - 1.0f) * 100.0f;
            #pragma unroll
            for (int i = 0; i < 4; i++) acc[i][j] += bias;
        }

        float alpha[4];
        #pragma unroll
        for (int i = 0; i < 4; i++) {
            float cm = fmaxf(fmaxf(acc[i][0], acc[i][1]), fmaxf(acc[i][2], acc[i][3]));
            #pragma unroll
            for (int o = 1; o < 16; o <<= 1)
                cm = fmaxf(cm, __shfl_xor_sync(0xffffffffu, cm, o));
            const float mn = fmaxf(m[i], cm);
            alpha[i] = __expf(m[i] - mn);
            float cl = 0.f;
            #pragma unroll
            for (int j = 0; j < 4; j++) {
                const float p = __expf(acc[i][j] - mn);
                acc[i][j] = p;
                cl += p;
            }
            #pragma unroll
            for (int o = 1; o < 16; o <<= 1)
                cl += __shfl_xor_sync(0xffffffffu, cl, o);
            l[i] = l[i] * alpha[i] + cl;
            m[i] = mn;
            #pragma unroll
            for (int j = 0; j < 4; j++) O[i][j] *= alpha[i];
        }

        __syncthreads();
        #pragma unroll
        for (int i = 0; i < 4; i++)
            #pragma unroll
            for (int j = 0; j < 4; j++)
                ks_t[(tq * 4 + i) * 64 + tx * 4 + j] = acc[i][j];
        __syncthreads();

        #pragma unroll 8
        for (int k = 0; k < 64; k++) {
            float p0 = ks_t[(tq * 4 + 0) * 64 + k];
            float p1 = ks_t[(tq * 4 + 1) * 64 + k];
            float p2 = ks_t[(tq * 4 + 2) * 64 + k];
            float p3 = ks_t[(tq * 4 + 3) * 64 + k];
            float4 vv = *reinterpret_cast<const float4*>(vs + k * 64 + tx * 4);
            float v4[4] = {vv.x, vv.y, vv.z, vv.w};
            #pragma unroll
            for (int j = 0; j < 4; j++) {
                O[0][j] += p0 * v4[j];
                O[1][j] += p1 * v4[j];
                O[2][j] += p2 * v4[j];
                O[3][j] += p3 * v4[j];
            }
        }
    }

    float* po = g_pO + ((size_t)(bh * NSPLIT + sp) * N2) * DH;
    #pragma unroll
    for (int i = 0; i < 4; i++) {
        *reinterpret_cast<float4*>(po + (size_t)(tq * 4 + i) * DH + tx * 4) =
            make_float4(O[i][0], O[i][1], O[i][2], O[i][3]);
    }
    if (tx == 0) {
        float* pml = g_pml + (size_t)(bh * NSPLIT + sp) * 2 * N2;
        #pragma unroll
        for (int i = 0; i < 4; i++) {
            pml[tq * 4 + i]      = m[i];
            pml[N2 + tq * 4 + i] = l[i];
        }
    }
}

// ---------------------------------------------------------------------------
// Merge partials -> g_attnh (half; feeds fp16 Out GEMM)
// ---------------------------------------------------------------------------
__global__ __launch_bounds__(256) void attn_merge()
{
    const int bh = blockIdx.x;
    const int b = bh / HEADS;
    const int h = bh - b * HEADS;
    const int tid = threadIdx.x;
    const int q  = tid >> 2;
    const int dq = tid & 3;

    float ms[NSPLIT], ls[NSPLIT];
    float M = -1e30f;
    #pragma unroll
    for (int s = 0; s < NSPLIT; s++) {
        const float* pml = g_pml + (size_t)(bh * NSPLIT + s) * 2 * N2;
        ms[s] = pml[q];
        ls[s] = pml[N2 + q];
        M = fmaxf(M, ms[s]);
    }
    float w[NSPLIT], lt = 0.f;
    #pragma unroll
    for (int s = 0; s < NSPLIT; s++) {
        w[s] = __expf(ms[s] - M);
        lt += ls[s] * w[s];
    }
    const float inv = 1.0f / lt;

    __half* dst = g_attnh + ((size_t)(b * N2 + q)) * DIM + h * DH + dq * 16;
    #pragma unroll
    for (int j = 0; j < 4; j++) {
        float4 acc = make_float4(0.f, 0.f, 0.f, 0.f);
        #pragma unroll
        for (int s = 0; s < NSPLIT; s++) {
            const float4 v = *reinterpret_cast<const float4*>(
                g_pO + ((size_t)(bh * NSPLIT + s) * N2 + q) * DH + dq * 16 + j * 4);
            acc.x += w[s] * v.x;
            acc.y += w[s] * v.y;
            acc.z += w[s] * v.z;
            acc.w += w[s] * v.w;
        }
        __half2 h0 = make_half2(__float2half_rn(acc.x * inv), __float2half_rn(acc.y * inv));
        __half2 h1 = make_half2(__float2half_rn(acc.z * inv), __float2half_rn(acc.w * inv));
        *reinterpret_cast<__half2*>(dst + j * 4)     = h0;
        *reinterpret_cast<__half2*>(dst + j * 4 + 2) = h1;
    }
}

// ---------------------------------------------------------------------------
// Launch
// ---------------------------------------------------------------------------
extern "C" void kernel_launch(void* const* d_in, const int* in_sizes, int n_in,
                              void* d_out, int out_size)
{
    const float* x       = (const float*)d_in[0];
    const float* latents = (const float*)d_in[1];
    const float* mask    = (const float*)d_in[2];
    const float* ln1g    = (const float*)d_in[3];
    const float* ln1b    = (const float*)d_in[4];
    const float* ln2g    = (const float*)d_in[5];
    const float* ln2b    = (const float*)d_in[6];
    const float* Wq      = (const float*)d_in[7];
    const float* Wkv     = (const float*)d_in[8];
    const float* Wout    = (const float*)d_in[9];
    float* out = (float*)d_out;

    __half *p_kvin, *p_lnh, *p_attnh, *p_wkvT, *p_wqT, *p_woT;
    float  *p_q, *p_kv;
    cudaGetSymbolAddress((void**)&p_kvin,  g_kvin);
    cudaGetSymbolAddress((void**)&p_lnh,   g_lnh);
    cudaGetSymbolAddress((void**)&p_q,     g_q);
    cudaGetSymbolAddress((void**)&p_kv,    g_kv);
    cudaGetSymbolAddress((void**)&p_attnh, g_attnh);
    cudaGetSymbolAddress((void**)&p_wkvT,  g_wkvT);
    cudaGetSymbolAddress((void**)&p_wqT,   g_wqT);
    cudaGetSymbolAddress((void**)&p_woT,   g_woT);

    static bool attr_set = false;
    if (!attr_set) {
        cudaFuncSetAttribute(gemm_tc, cudaFuncAttributeMaxDynamicSharedMemorySize,
                             GEMM_SMEM_BYTES);
        attr_set = true;
    }

    // 0) Transpose + fp16-round weights
    transpose_kernel<<<dim3(2 * DIM / 32, DIM / 32), dim3(32, 8)>>>(Wkv, p_wkvT, 2 * DIM);
    transpose_kernel<<<dim3(DIM / 32, DIM / 32), dim3(32, 8)>>>(Wq, p_wqT, DIM);
    transpose_kernel<<<dim3(DIM / 32, DIM / 32), dim3(32, 8)>>>(Wout, p_woT, DIM);

    // 1) LayerNorms (half outputs)
    ln_kernel<<<MROWS, 256>>>(x, latents, ln1g, ln1b, ln2g, ln2b);

    // 2) KV GEMM (fp16 mma): (33280 x 1024) @ (1024 x 2048)
    gemm_tc<<<dim3(2 * DIM / 128, MROWS / 128), 256, GEMM_SMEM_BYTES>>>(
        p_kvin, p_wkvT, p_kv, 2 * DIM);

    // 3) Q GEMM (fp16 mma): (512 x 1024) @ (1024 x 1024)
    gemm_tc<<<dim3(DIM / 128, BATCH * N2 / 128), 256, GEMM_SMEM_BYTES>>>(
        p_lnh, p_wqT, p_q, DIM);

    // 4) Attention: split-K partials + merge (half output)
    attn_partial<<<dim3(HEADS, BATCH, NSPLIT), 256>>>(mask);
    attn_merge<<<BATCH * HEADS, 256>>>();

    // 5) Out GEMM (fp16 mma) -> d_out
    gemm_tc<<<dim3(DIM / 128, BATCH * N2 / 128), 256, GEMM_SMEM_BYTES>>>(
        p_attnh, p_woT, out, DIM);
}

// round 6
// speedup vs baseline: 4.5771x; 1.0618x over previous
#include <cuda_runtime.h>
#include <cuda_fp16.h>
#include <cstdint>

// ---------------------------------------------------------------------------
// PerceiverAttention, sm_103 — Round 5:
//   * gemm_tc: fp16 mma.sync + ldmatrix fragment loads (4x fewer shared ops)
//   * g_kv stored fp16 (templated epilogue); attention converts on load
// ---------------------------------------------------------------------------

#define BATCH 8
#define N1 4096
#define N2 64
#define NKEYS 4160
#define DIM 1024
#define HEADS 16
#define DH 64
#define MROWS (BATCH * NKEYS)   // 33280
#define NSPLIT 5
#define CH_PER_SPLIT 13

__device__ __half g_kvin[(size_t)MROWS * DIM];
__device__ __half g_lnh [(size_t)BATCH * N2 * DIM];
__device__ float  g_q   [(size_t)BATCH * N2 * DIM];
__device__ __half g_kvh [(size_t)MROWS * 2 * DIM];    // k|v, fp16
__device__ __half g_attnh[(size_t)BATCH * N2 * DIM];
__device__ __half g_wkvT[(size_t)2 * DIM * DIM];
__device__ __half g_wqT [(size_t)DIM * DIM];
__device__ __half g_woT [(size_t)DIM * DIM];
__device__ float  g_pO  [(size_t)BATCH * HEADS * NSPLIT * N2 * DH];
__device__ float  g_pml [(size_t)BATCH * HEADS * NSPLIT * 2 * N2];

// ---------------------------------------------------------------------------
// Helpers
// ---------------------------------------------------------------------------
__device__ __forceinline__ uint32_t smem_u32(const void* p) {
    uint32_t a;
    asm("{ .reg .u64 t; cvta.to.shared.u64 t, %1; cvt.u32.u64 %0, t; }" : "=r"(a) : "l"(p));
    return a;
}
__device__ __forceinline__ void cp_async16(uint32_t dst, const void* src) {
    asm volatile("cp.async.cg.shared.global [%0], [%1], 16;" :: "r"(dst), "l"(src));
}
__device__ __forceinline__ void cp_commit() {
    asm volatile("cp.async.commit_group;" ::: "memory");
}
template <int N>
__device__ __forceinline__ void cp_wait() {
    asm volatile("cp.async.wait_group %0;" :: "n"(N) : "memory");
}
__device__ __forceinline__ void mma_f16(float* d, const uint32_t* a, const uint32_t* b) {
    asm volatile(
        "mma.sync.aligned.m16n8k16.row.col.f32.f16.f16.f32 "
        "{%0,%1,%2,%3}, {%4,%5,%6,%7}, {%8,%9}, {%0,%1,%2,%3};"
        : "+f"(d[0]), "+f"(d[1]), "+f"(d[2]), "+f"(d[3])
        : "r"(a[0]), "r"(a[1]), "r"(a[2]), "r"(a[3]), "r"(b[0]), "r"(b[1]));
}
__device__ __forceinline__ void ldm_x4(uint32_t* r, uint32_t addr) {
    asm volatile("ldmatrix.sync.aligned.m8n8.x4.shared.b16 {%0,%1,%2,%3}, [%4];"
        : "=r"(r[0]), "=r"(r[1]), "=r"(r[2]), "=r"(r[3]) : "r"(addr));
}
__device__ __forceinline__ void store_pair(float* p, float a, float b) {
    *reinterpret_cast<float2*>(p) = make_float2(a, b);
}
__device__ __forceinline__ void store_pair(__half* p, float a, float b) {
    *reinterpret_cast<__half2*>(p) = make_half2(__float2half_rn(a), __float2half_rn(b));
}

// ---------------------------------------------------------------------------
// Weight transpose + fp16 round
// ---------------------------------------------------------------------------
__global__ __launch_bounds__(256) void transpose_kernel(
    const float* __restrict__ in, __half* __restrict__ out, int ncols)
{
    __shared__ float t[32][33];
    const int bx = blockIdx.x * 32;
    const int by = blockIdx.y * 32;
    const int x = threadIdx.x;
    const int y = threadIdx.y;
    #pragma unroll
    for (int i = 0; i < 32; i += 8)
        t[y + i][x] = in[(size_t)(by + y + i) * ncols + bx + x];
    __syncthreads();
    #pragma unroll
    for (int i = 0; i < 32; i += 8)
        out[(size_t)(bx + y + i) * DIM + by + x] = __float2half_rn(t[x][y + i]);
}

// ---------------------------------------------------------------------------
// LayerNorm -> half outputs
// ---------------------------------------------------------------------------
__global__ __launch_bounds__(256) void ln_kernel(
    const float* __restrict__ x, const float* __restrict__ lat,
    const float* __restrict__ g1, const float* __restrict__ b1,
    const float* __restrict__ g2, const float* __restrict__ b2)
{
    __shared__ float red[16];
    const int r  = blockIdx.x;
    const int bb = r / NKEYS;
    const int i  = r - bb * NKEYS;

    const float* src;
    const float* g;
    const float* be;
    __half* dst2 = nullptr;
    if (i < N1) {
        src = x + ((size_t)bb * N1 + i) * DIM;
        g = g1; be = b1;
    } else {
        const int j = i - N1;
        src = lat + ((size_t)bb * N2 + j) * DIM;
        g = g2; be = b2;
        dst2 = g_lnh + ((size_t)bb * N2 + j) * DIM;
    }
    __half* dst = g_kvin + (size_t)r * DIM;

    const int t = threadIdx.x;
    float4 v = reinterpret_cast<const float4*>(src)[t];
    float s  = v.x + v.y + v.z + v.w;
    float sq = v.x * v.x + v.y * v.y + v.z * v.z + v.w * v.w;
    #pragma unroll
    for (int o = 16; o > 0; o >>= 1) {
        s  += __shfl_xor_sync(0xffffffffu, s, o);
        sq += __shfl_xor_sync(0xffffffffu, sq, o);
    }
    if ((t & 31) == 0) { red[t >> 5] = s; red[8 + (t >> 5)] = sq; }
    __syncthreads();
    float S = 0.f, SQ = 0.f;
    #pragma unroll
    for (int k = 0; k < 8; k++) { S += red[k]; SQ += red[8 + k]; }

    const float mu   = S * (1.0f / DIM);
    const float var  = SQ * (1.0f / DIM) - mu * mu;
    const float rstd = rsqrtf(var + 1e-5f);

    float4 gv = reinterpret_cast<const float4*>(g)[t];
    float4 bv = reinterpret_cast<const float4*>(be)[t];
    __half2 h0 = make_half2(__float2half_rn((v.x - mu) * rstd * gv.x + bv.x),
                            __float2half_rn((v.y - mu) * rstd * gv.y + bv.y));
    __half2 h1 = make_half2(__float2half_rn((v.z - mu) * rstd * gv.z + bv.z),
                            __float2half_rn((v.w - mu) * rstd * gv.w + bv.w));
    reinterpret_cast<__half2*>(dst)[t * 2]     = h0;
    reinterpret_cast<__half2*>(dst)[t * 2 + 1] = h1;
    if (dst2) {
        reinterpret_cast<__half2*>(dst2)[t * 2]     = h0;
        reinterpret_cast<__half2*>(dst2)[t * 2 + 1] = h1;
    }
}

// ---------------------------------------------------------------------------
// fp16 mma.sync GEMM with ldmatrix fragment loads.
// C[M x N] = A[M x 1024] @ Bt[N x 1024]^T, CTA tile 128x128, K-chunk 64.
// ---------------------------------------------------------------------------
#define PADH 72
#define TILE_H (128 * PADH)
#define NSTAGE 3
#define GEMM_SMEM_BYTES (NSTAGE * 2 * TILE_H * 2)   // 110592

template <typename OutT>
__global__ __launch_bounds__(256, 2) void gemm_tc(
    const __half* __restrict__ A, const __half* __restrict__ Bt,
    OutT* __restrict__ C, int ldc)
{
    extern __shared__ __half smh[];
    const uint32_t sb = smem_u32(smh);

    const int tid  = threadIdx.x;
    const int wid  = tid >> 5;
    const int lane = tid & 31;
    const int wm = wid & 3;
    const int wn = wid >> 2;
    const int m0 = blockIdx.y * 128;
    const int n0 = blockIdx.x * 128;

    const __half* ga = A  + (size_t)m0 * DIM;
    const __half* gb = Bt + (size_t)n0 * DIM;

    const int lr = tid >> 3;
    const int lc = tid & 7;

    float acc[2][8][4];
    #pragma unroll
    for (int i = 0; i < 2; i++)
        #pragma unroll
        for (int j = 0; j < 8; j++)
            #pragma unroll
            for (int q = 0; q < 4; q++) acc[i][j][q] = 0.f;

    // ldmatrix per-thread base offsets (halves, within a stage tile)
    // A (x4 over 16x16): lanes 0-15 -> rows m0-15 @k0; lanes 16-31 -> same rows @k+8
    const uint32_t a_off = (uint32_t)(wm * 32 + (lane & 15)) * PADH + (lane >> 4) * 8;
    // B (x4 over two n-groups x k16): lanes 0-7 n0-7@k0, 8-15 n0-7@k8,
    //                                 16-23 n8-15@k0, 24-31 n8-15@k8
    const uint32_t b_off = (uint32_t)(wn * 64 + ((lane >> 4) << 3) + (lane & 7)) * PADH
                         + ((lane >> 3) & 1) * 8;

    auto load_tile = [&](int chunk, int stage) {
        const uint32_t abase = sb + (uint32_t)stage * 2 * TILE_H * 2;
        const uint32_t bbase = abase + TILE_H * 2;
        const int k0 = chunk * 64;
        #pragma unroll
        for (int i = 0; i < 4; i++) {
            const int r = lr + i * 32;
            cp_async16(abase + (r * PADH + lc * 8) * 2, ga + (size_t)r * DIM + k0 + lc * 8);
        }
        #pragma unroll
        for (int i = 0; i < 4; i++) {
            const int r = lr + i * 32;
            cp_async16(bbase + (r * PADH + lc * 8) * 2, gb + (size_t)r * DIM + k0 + lc * 8);
        }
        cp_commit();
    };

    const int NCHUNK = DIM / 64;   // 16
    load_tile(0, 0);
    load_tile(1, 1);

    for (int c = 0; c < NCHUNK; c++) {
        const int stage = c % NSTAGE;
        if (c + 2 < NCHUNK) { load_tile(c + 2, (c + 2) % NSTAGE); cp_wait<2>(); }
        else if (c + 2 == NCHUNK) { cp_wait<1>(); }
        else { cp_wait<0>(); }
        __syncthreads();

        const uint32_t sA = sb + (uint32_t)stage * 2 * TILE_H * 2;
        const uint32_t sB = sA + TILE_H * 2;

        #pragma unroll
        for (int kk = 0; kk < 4; kk++) {          // k-step of 16 halves
            uint32_t af[2][4], bf[8][2];
            #pragma unroll
            for (int mt = 0; mt < 2; mt++)
                ldm_x4(af[mt], sA + (a_off + (uint32_t)(mt * 16) * PADH + kk * 16) * 2);
            #pragma unroll
            for (int p = 0; p < 4; p++) {
                uint32_t r4[4];
                ldm_x4(r4, sB + (b_off + (uint32_t)(p * 16) * PADH + kk * 16) * 2);
                bf[2 * p][0]     = r4[0];
                bf[2 * p][1]     = r4[1];
                bf[2 * p + 1][0] = r4[2];
                bf[2 * p + 1][1] = r4[3];
            }
            #pragma unroll
            for (int mt = 0; mt < 2; mt++)
                #pragma unroll
                for (int nt = 0; nt < 8; nt++)
                    mma_f16(acc[mt][nt], af[mt], bf[nt]);
        }
        __syncthreads();
    }

    #pragma unroll
    for (int mt = 0; mt < 2; mt++) {
        const int row = m0 + wm * 32 + mt * 16 + (lane >> 2);
        #pragma unroll
        for (int nt = 0; nt < 8; nt++) {
            const int col = n0 + wn * 64 + nt * 8 + (lane & 3) * 2;
            store_pair(C + (size_t)row * ldc + col, acc[mt][nt][0], acc[mt][nt][1]);
            store_pair(C + (size_t)(row + 8) * ldc + col, acc[mt][nt][2], acc[mt][nt][3]);
        }
    }
}

// ---------------------------------------------------------------------------
// Split-K flash attention (fp32 compute; KV loaded as half)
// ---------------------------------------------------------------------------
__global__ __launch_bounds__(256) void attn_partial(const float* __restrict__ mask)
{
    __shared__ float qs_t[64 * 64];
    __shared__ float ks_t[64 * 64];
    __shared__ float vs  [64 * 64];

    const int h = blockIdx.x;
    const int b = blockIdx.y;
    const int sp = blockIdx.z;
    const int bh = b * HEADS + h;
    const int tid = threadIdx.x;
    const int tq = tid >> 4;
    const int tx = tid & 15;

    {
        const int qr = tid >> 2;
        const int dg = tid & 3;
        const float4* src = reinterpret_cast<const float4*>(
            g_q + ((size_t)(b * N2 + qr)) * DIM + h * DH + dg * 16);
        #pragma unroll
        for (int ii = 0; ii < 4; ii++) {
            float4 v = src[ii];
            const int d0 = dg * 16 + ii * 4;
            qs_t[(d0 + 0) * 64 + qr] = v.x * 0.125f;
            qs_t[(d0 + 1) * 64 + qr] = v.y * 0.125f;
            qs_t[(d0 + 2) * 64 + qr] = v.z * 0.125f;
            qs_t[(d0 + 3) * 64 + qr] = v.w * 0.125f;
        }
    }

    float O[4][4] = {};
    float m[4], l[4];
    #pragma unroll
    for (int i = 0; i < 4; i++) { m[i] = -1e30f; l[i] = 0.f; }

    const size_t kvbase = (size_t)b * NKEYS * (2 * DIM);

    for (int cc = 0; cc < CH_PER_SPLIT; cc++) {
        const int key0 = (sp * CH_PER_SPLIT + cc) * 64;
        __syncthreads();

        {
            const int kl = tid >> 2;
            const int dg = tid & 3;
            const uint4* ksrc = reinterpret_cast<const uint4*>(
                g_kvh + kvbase + (size_t)(key0 + kl) * (2 * DIM) + h * DH + dg * 16);
            #pragma unroll
            for (int part = 0; part < 2; part++) {
                uint4 u = ksrc[part];
                const __half2* hp = reinterpret_cast<const __half2*>(&u);
                const int d0 = dg * 16 + part * 8;
                #pragma unroll
                for (int j = 0; j < 4; j++) {
                    float2 f = __half22float2(hp[j]);
                    ks_t[(d0 + 2 * j) * 64 + kl]     = f.x;
                    ks_t[(d0 + 2 * j + 1) * 64 + kl] = f.y;
                }
            }
            const uint4* vsrc = reinterpret_cast<const uint4*>(
                g_kvh + kvbase + (size_t)(key0 + kl) * (2 * DIM) + DIM + h * DH + dg * 16);
            #pragma unroll
            for (int part = 0; part < 2; part++) {
                uint4 u = vsrc[part];
                const __half2* hp = reinterpret_cast<const __half2*>(&u);
                const int d0 = dg * 16 + part * 8;
                #pragma unroll
                for (int j = 0; j < 4; j++) {
                    float2 f = __half22float2(hp[j]);
                    vs[kl * 64 + d0 + 2 * j]     = f.x;
                    vs[kl * 64 + d0 + 2 * j + 1] = f.y;
                }
            }
        }
        __syncthreads();

        float acc[4][4] = {};
        #pragma unroll 8
        for (int d = 0; d < 64; d++) {
            float4 av = *reinterpret_cast<const float4*>(qs_t + d * 64 + tq * 4);
            float4 bv = *reinterpret_cast<const float4*>(ks_t + d * 64 + tx * 4);
            float a[4] = {av.x, av.y, av.z, av.w};
            float kb[4] = {bv.x, bv.y, bv.z, bv.w};
            #pragma unroll
            for (int i = 0; i < 4; i++)
                #pragma unroll
                for (int j = 0; j < 4; j++)
                    acc[i][j] += a[i] * kb[j];
        }

        #pragma unroll
        for (int j = 0; j < 4; j++) {
            const int kg = key0 + tx * 4 + j;
            float bias = 0.f;
            if (kg < N1) bias = (mask[(size_t)b * N1 + kg] - 1.0f) * 100.0f;
            #pragma unroll
            for (int i = 0; i < 4; i++) acc[i][j] += bias;
        }

        float alpha[4];
        #pragma unroll
        for (int i = 0; i < 4; i++) {
            float cm = fmaxf(fmaxf(acc[i][0], acc[i][1]), fmaxf(acc[i][2], acc[i][3]));
            #pragma unroll
            for (int o = 1; o < 16; o <<= 1)
                cm = fmaxf(cm, __shfl_xor_sync(0xffffffffu, cm, o));
            const float mn = fmaxf(m[i], cm);
            alpha[i] = __expf(m[i] - mn);
            float cl = 0.f;
            #pragma unroll
            for (int j = 0; j < 4; j++) {
                const float p = __expf(acc[i][j] - mn);
                acc[i][j] = p;
                cl += p;
            }
            #pragma unroll
            for (int o = 1; o < 16; o <<= 1)
                cl += __shfl_xor_sync(0xffffffffu, cl, o);
            l[i] = l[i] * alpha[i] + cl;
            m[i] = mn;
            #pragma unroll
            for (int j = 0; j < 4; j++) O[i][j] *= alpha[i];
        }

        __syncthreads();
        #pragma unroll
        for (int i = 0; i < 4; i++)
            #pragma unroll
            for (int j = 0; j < 4; j++)
                ks_t[(tq * 4 + i) * 64 + tx * 4 + j] = acc[i][j];
        __syncthreads();

        #pragma unroll 8
        for (int k = 0; k < 64; k++) {
            float p0 = ks_t[(tq * 4 + 0) * 64 + k];
            float p1 = ks_t[(tq * 4 + 1) * 64 + k];
            float p2 = ks_t[(tq * 4 + 2) * 64 + k];
            float p3 = ks_t[(tq * 4 + 3) * 64 + k];
            float4 vv = *reinterpret_cast<const float4*>(vs + k * 64 + tx * 4);
            float v4[4] = {vv.x, vv.y, vv.z, vv.w};
            #pragma unroll
            for (int j = 0; j < 4; j++) {
                O[0][j] += p0 * v4[j];
                O[1][j] += p1 * v4[j];
                O[2][j] += p2 * v4[j];
                O[3][j] += p3 * v4[j];
            }
        }
    }

    float* po = g_pO + ((size_t)(bh * NSPLIT + sp) * N2) * DH;
    #pragma unroll
    for (int i = 0; i < 4; i++) {
        *reinterpret_cast<float4*>(po + (size_t)(tq * 4 + i) * DH + tx * 4) =
            make_float4(O[i][0], O[i][1], O[i][2], O[i][3]);
    }
    if (tx == 0) {
        float* pml = g_pml + (size_t)(bh * NSPLIT + sp) * 2 * N2;
        #pragma unroll
        for (int i = 0; i < 4; i++) {
            pml[tq * 4 + i]      = m[i];
            pml[N2 + tq * 4 + i] = l[i];
        }
    }
}

// ---------------------------------------------------------------------------
// Merge partials -> g_attnh (half)
// ---------------------------------------------------------------------------
__global__ __launch_bounds__(256) void attn_merge()
{
    const int bh = blockIdx.x;
    const int b = bh / HEADS;
    const int h = bh - b * HEADS;
    const int tid = threadIdx.x;
    const int q  = tid >> 2;
    const int dq = tid & 3;

    float ms[NSPLIT], ls[NSPLIT];
    float M = -1e30f;
    #pragma unroll
    for (int s = 0; s < NSPLIT; s++) {
        const float* pml = g_pml + (size_t)(bh * NSPLIT + s) * 2 * N2;
        ms[s] = pml[q];
        ls[s] = pml[N2 + q];
        M = fmaxf(M, ms[s]);
    }
    float w[NSPLIT], lt = 0.f;
    #pragma unroll
    for (int s = 0; s < NSPLIT; s++) {
        w[s] = __expf(ms[s] - M);
        lt += ls[s] * w[s];
    }
    const float inv = 1.0f / lt;

    __half* dst = g_attnh + ((size_t)(b * N2 + q)) * DIM + h * DH + dq * 16;
    #pragma unroll
    for (int j = 0; j < 4; j++) {
        float4 acc = make_float4(0.f, 0.f, 0.f, 0.f);
        #pragma unroll
        for (int s = 0; s < NSPLIT; s++) {
            const float4 v = *reinterpret_cast<const float4*>(
                g_pO + ((size_t)(bh * NSPLIT + s) * N2 + q) * DH + dq * 16 + j * 4);
            acc.x += w[s] * v.x;
            acc.y += w[s] * v.y;
            acc.z += w[s] * v.z;
            acc.w += w[s] * v.w;
        }
        __half2 h0 = make_half2(__float2half_rn(acc.x * inv), __float2half_rn(acc.y * inv));
        __half2 h1 = make_half2(__float2half_rn(acc.z * inv), __float2half_rn(acc.w * inv));
        *reinterpret_cast<__half2*>(dst + j * 4)     = h0;
        *reinterpret_cast<__half2*>(dst + j * 4 + 2) = h1;
    }
}

// ---------------------------------------------------------------------------
// Launch
// ---------------------------------------------------------------------------
extern "C" void kernel_launch(void* const* d_in, const int* in_sizes, int n_in,
                              void* d_out, int out_size)
{
    const float* x       = (const float*)d_in[0];
    const float* latents = (const float*)d_in[1];
    const float* mask    = (const float*)d_in[2];
    const float* ln1g    = (const float*)d_in[3];
    const float* ln1b    = (const float*)d_in[4];
    const float* ln2g    = (const float*)d_in[5];
    const float* ln2b    = (const float*)d_in[6];
    const float* Wq      = (const float*)d_in[7];
    const float* Wkv     = (const float*)d_in[8];
    const float* Wout    = (const float*)d_in[9];
    float* out = (float*)d_out;

    __half *p_kvin, *p_lnh, *p_kvh, *p_attnh, *p_wkvT, *p_wqT, *p_woT;
    float  *p_q;
    cudaGetSymbolAddress((void**)&p_kvin,  g_kvin);
    cudaGetSymbolAddress((void**)&p_lnh,   g_lnh);
    cudaGetSymbolAddress((void**)&p_q,     g_q);
    cudaGetSymbolAddress((void**)&p_kvh,   g_kvh);
    cudaGetSymbolAddress((void**)&p_attnh, g_attnh);
    cudaGetSymbolAddress((void**)&p_wkvT,  g_wkvT);
    cudaGetSymbolAddress((void**)&p_wqT,   g_wqT);
    cudaGetSymbolAddress((void**)&p_woT,   g_woT);

    static bool attr_set = false;
    if (!attr_set) {
        cudaFuncSetAttribute(gemm_tc<__half>, cudaFuncAttributeMaxDynamicSharedMemorySize,
                             GEMM_SMEM_BYTES);
        cudaFuncSetAttribute(gemm_tc<float>, cudaFuncAttributeMaxDynamicSharedMemorySize,
                             GEMM_SMEM_BYTES);
        attr_set = true;
    }

    // 0) Transpose + fp16-round weights
    transpose_kernel<<<dim3(2 * DIM / 32, DIM / 32), dim3(32, 8)>>>(Wkv, p_wkvT, 2 * DIM);
    transpose_kernel<<<dim3(DIM / 32, DIM / 32), dim3(32, 8)>>>(Wq, p_wqT, DIM);
    transpose_kernel<<<dim3(DIM / 32, DIM / 32), dim3(32, 8)>>>(Wout, p_woT, DIM);

    // 1) LayerNorms (half outputs)
    ln_kernel<<<MROWS, 256>>>(x, latents, ln1g, ln1b, ln2g, ln2b);

    // 2) KV GEMM (fp16 mma, half output)
    gemm_tc<__half><<<dim3(2 * DIM / 128, MROWS / 128), 256, GEMM_SMEM_BYTES>>>(
        p_kvin, p_wkvT, p_kvh, 2 * DIM);

    // 3) Q GEMM (fp16 mma, float output)
    gemm_tc<float><<<dim3(DIM / 128, BATCH * N2 / 128), 256, GEMM_SMEM_BYTES>>>(
        p_lnh, p_wqT, p_q, DIM);

    // 4) Attention: split-K partials + merge (half output)
    attn_partial<<<dim3(HEADS, BATCH, NSPLIT), 256>>>(mask);
    attn_merge<<<BATCH * HEADS, 256>>>();

    // 5) Out GEMM (fp16 mma, float output) -> d_out
    gemm_tc<float><<<dim3(DIM / 128, BATCH * N2 / 128), 256, GEMM_SMEM_BYTES>>>(
        p_attnh, p_woT, out, DIM);
}